// round 6
// baseline (speedup 1.0000x reference)
#include <cuda_runtime.h>
#include <cuda_fp16.h>
#include <cuda_bf16.h>
#include <cstdint>

#define Nn     8192
#define FIN    512
#define FOUT   256
#define LALPHA 0.2f
#define NSPLIT 2
#define M_TILE 128
#define KC     64
#define JHALF  (Nn / NSPLIT)      // 4096
#define NCHUNK (JHALF / KC)       // 64

// smem word-strides (uint32 units)
#define WTW 36   // WhT tile: 256 rows x (32 half2 + 4 pad)
#define PSW 36   // P  tile: 128 rows x (32 half2 + 4 pad)

// ---------------- scratch (device globals: allowed) ----------------
__device__ float  d_Wh[(size_t)Nn * FOUT];           // 8 MB fp32
__device__ __half d_WhhT[(size_t)FOUT * Nn];         // 4 MB half, [n][j]
__device__ float  d_f1[Nn];
__device__ float  d_f2[Nn];
__device__ float  d_A[Nn];   // exp(f1+gm-m)
__device__ float  d_C[Nn];   // exp(0.2(f1+gm)-m)
__device__ float  d_B[Nn];   // exp(f2-gm)
__device__ float  d_D[Nn];   // exp(0.2(f2-gm))
__device__ int    d_gmaxkey;
__device__ float  d_accpart[(size_t)NSPLIT * Nn * FOUT];  // 16 MB
__device__ float  d_spart[(size_t)NSPLIT * Nn];

__device__ __forceinline__ void mma_f16(float* d, uint32_t a0, uint32_t a1,
                                        uint32_t a2, uint32_t a3,
                                        uint32_t b0, uint32_t b1) {
    asm volatile(
        "mma.sync.aligned.m16n8k16.row.col.f32.f16.f16.f32 "
        "{%0,%1,%2,%3}, {%4,%5,%6,%7}, {%8,%9}, {%0,%1,%2,%3};"
        : "+f"(d[0]), "+f"(d[1]), "+f"(d[2]), "+f"(d[3])
        : "r"(a0), "r"(a1), "r"(a2), "r"(a3), "r"(b0), "r"(b1));
}

// ---------------- Wh = h @ W ----------------
__global__ void gemm_wh(const float* __restrict__ h, const float* __restrict__ W) {
    if (blockIdx.x == 0 && blockIdx.y == 0 && threadIdx.x == 0)
        d_gmaxkey = (int)0x80000000;
    __shared__ float As[16][64];
    __shared__ float Bs[16][64];
    int t  = threadIdx.x;
    int bm = blockIdx.x * 64, bn = blockIdx.y * 64;
    int r0 = (t >> 4) * 4, c0 = (t & 15) * 4;
    int arow = t >> 2, akq = (t & 3) * 4;
    int bkk = t >> 4, bn4 = (t & 15) * 4;

    float acc[4][4];
#pragma unroll
    for (int i = 0; i < 4; i++)
#pragma unroll
        for (int j = 0; j < 4; j++) acc[i][j] = 0.f;

    for (int k0 = 0; k0 < FIN; k0 += 16) {
        float4 av = *(const float4*)&h[(size_t)(bm + arow) * FIN + k0 + akq];
        As[akq + 0][arow] = av.x; As[akq + 1][arow] = av.y;
        As[akq + 2][arow] = av.z; As[akq + 3][arow] = av.w;
        *(float4*)&Bs[bkk][bn4] = *(const float4*)&W[(size_t)(k0 + bkk) * FOUT + bn + bn4];
        __syncthreads();
#pragma unroll
        for (int kk = 0; kk < 16; kk++) {
            float4 a4 = *(float4*)&As[kk][r0];
            float4 b4 = *(float4*)&Bs[kk][c0];
            acc[0][0] += a4.x * b4.x; acc[0][1] += a4.x * b4.y;
            acc[0][2] += a4.x * b4.z; acc[0][3] += a4.x * b4.w;
            acc[1][0] += a4.y * b4.x; acc[1][1] += a4.y * b4.y;
            acc[1][2] += a4.y * b4.z; acc[1][3] += a4.y * b4.w;
            acc[2][0] += a4.z * b4.x; acc[2][1] += a4.z * b4.y;
            acc[2][2] += a4.z * b4.z; acc[2][3] += a4.z * b4.w;
            acc[3][0] += a4.w * b4.x; acc[3][1] += a4.w * b4.y;
            acc[3][2] += a4.w * b4.z; acc[3][3] += a4.w * b4.w;
        }
        __syncthreads();
    }
#pragma unroll
    for (int i = 0; i < 4; i++)
        *(float4*)&d_Wh[(size_t)(bm + r0 + i) * FOUT + bn + c0] =
            make_float4(acc[i][0], acc[i][1], acc[i][2], acc[i][3]);
}

// ---------------- Wh -> half, transposed [FOUT][Nn] ----------------
__global__ void whconv() {
    __shared__ float tile[32][33];
    int bx = blockIdx.x * 32;   // Nn base
    int by = blockIdx.y * 32;   // FOUT base
    int tx = threadIdx.x & 31, ty4 = (threadIdx.x >> 5) * 4;
#pragma unroll
    for (int r = 0; r < 4; r++)
        tile[ty4 + r][tx] = d_Wh[(size_t)(bx + ty4 + r) * FOUT + by + tx];
    __syncthreads();
#pragma unroll
    for (int r = 0; r < 4; r++)
        d_WhhT[(size_t)(by + ty4 + r) * Nn + bx + tx] =
            __float2half(tile[tx][ty4 + r]);
}

// ---------------- f1, f2 and global max(f2) ----------------
__global__ void f12_kernel(const float* __restrict__ a) {
    int lane = threadIdx.x & 31, warp = threadIdx.x >> 5;
    int row  = blockIdx.x * 8 + warp;
    const float* wr = &d_Wh[(size_t)row * FOUT];
    float s1 = 0.f, s2 = 0.f;
#pragma unroll
    for (int q = 0; q < 2; q++) {
        int c = q * 128 + lane * 4;
        float4 v  = *(const float4*)&wr[c];
        float4 a1 = *(const float4*)&a[c];
        float4 a2 = *(const float4*)&a[FOUT + c];
        s1 += v.x * a1.x + v.y * a1.y + v.z * a1.z + v.w * a1.w;
        s2 += v.x * a2.x + v.y * a2.y + v.z * a2.z + v.w * a2.w;
    }
#pragma unroll
    for (int o = 16; o; o >>= 1) {
        s1 += __shfl_xor_sync(0xffffffffu, s1, o);
        s2 += __shfl_xor_sync(0xffffffffu, s2, o);
    }
    if (lane == 0) {
        d_f1[row] = s1;
        d_f2[row] = s2;
        int b   = __float_as_int(s2);
        int key = b >= 0 ? b : (b ^ 0x7fffffff);
        atomicMax(&d_gmaxkey, key);
    }
}

// ---------------- factorized softmax weights ----------------
// e=LReLU(f1_i+f2_j); m_i=LReLU(f1_i+gm)>=rowmax; exp(e-m)= s>0 ? A_i*B_j : C_i*D_j
__global__ void pexp_kernel() {
    int i = blockIdx.x * 256 + threadIdx.x;
    int kk = d_gmaxkey;
    float gm = __int_as_float(kk >= 0 ? kk : (kk ^ 0x7fffffff));
    float f1 = d_f1[i], f2 = d_f2[i];
    float u  = f1 + gm;
    float m  = u > 0.f ? u : LALPHA * u;
    d_A[i] = __expf(u - m);
    d_C[i] = __expf(LALPHA * u - m);
    float v = f2 - gm;
    d_B[i] = __expf(v);
    d_D[i] = __expf(LALPHA * v);
}

// ---------------- fused attention @ Wh via mma.sync fp16 ----------------
// 512 threads = 16 warps: 8 m-strips x 2 n-halves. Warp tile 16x128.
// Per 64-j chunk: stage WhT half tile [256][64] + P half tile [128][64],
// then 4 k16-steps x 16 n-tiles of m16n8k16.
#define SMEM_DYN (256 * WTW * 4 + 128 * PSW * 4)   // 36864 + 18432 = 55296

__global__ void __launch_bounds__(512, 1) attn_mma(const int* __restrict__ adj) {
    extern __shared__ char sm[];
    uint32_t* WhTs = (uint32_t*)sm;                   // [256][36] words (half2)
    uint32_t* Ps   = (uint32_t*)(sm + 256 * WTW * 4); // [128][36] words (half2)

    int t    = threadIdx.x;
    int lane = t & 31, wid = t >> 5;
    int mstrip = wid >> 1, nhalf = wid & 1;
    int i0    = blockIdx.x * M_TILE;
    int split = blockIdx.y;
    int jbeg  = split * JHALF;

    // P-phase: one row per 4 threads, 16 cols each
    int prow = t >> 2;
    int pc0  = (t & 3) << 4;
    float f1r = d_f1[i0 + prow];
    float Ar  = d_A[i0 + prow];
    float Cr  = d_C[i0 + prow];
    float ssum = 0.f;
    const int4* adjrow = (const int4*)(adj + (size_t)(i0 + prow) * Nn);

    float acc[16][4];
#pragma unroll
    for (int n = 0; n < 16; n++)
#pragma unroll
        for (int u = 0; u < 4; u++) acc[n][u] = 0.f;

    int gID = lane >> 2, tID = lane & 3;
    int arow0 = mstrip * 16 + gID;

    for (int c = 0; c < NCHUNK; c++) {
        int jg = jbeg + c * KC;

        // ---- stage WhT half tile [256 n][64 j] ----
#pragma unroll
        for (int u = 0; u < 4; u++) {
            int f = u * 512 + t;               // 0..2047
            int row = f >> 3, seg = f & 7;     // 8 x 16B per row
            uint4 v = *(const uint4*)&d_WhhT[(size_t)row * Nn + jg + seg * 8];
            *(uint4*)&WhTs[row * WTW + seg * 4] = v;
        }

        // ---- P half tile [128 i][64 j] ----
        uint32_t pk[8];
#pragma unroll
        for (int u = 0; u < 4; u++) {
            int cc = pc0 + u * 4;
            int4   ad  = adjrow[(jg + cc) >> 2];
            float4 f2v = *(const float4*)&d_f2[jg + cc];
            float4 Bv  = *(const float4*)&d_B[jg + cc];
            float4 Dv  = *(const float4*)&d_D[jg + cc];
            float s0 = f1r + f2v.x, s1 = f1r + f2v.y;
            float s2 = f1r + f2v.z, s3 = f1r + f2v.w;
            float p0 = (ad.x > 0) ? (s0 > 0.f ? Ar * Bv.x : Cr * Dv.x) : 0.f;
            float p1 = (ad.y > 0) ? (s1 > 0.f ? Ar * Bv.y : Cr * Dv.y) : 0.f;
            float p2 = (ad.z > 0) ? (s2 > 0.f ? Ar * Bv.z : Cr * Dv.z) : 0.f;
            float p3 = (ad.w > 0) ? (s3 > 0.f ? Ar * Bv.w : Cr * Dv.w) : 0.f;
            ssum += (p0 + p1) + (p2 + p3);
            __half2 h01 = __floats2half2_rn(p0, p1);
            __half2 h23 = __floats2half2_rn(p2, p3);
            pk[u * 2]     = *(uint32_t*)&h01;
            pk[u * 2 + 1] = *(uint32_t*)&h23;
        }
        {
            uint32_t* dst = &Ps[prow * PSW + (pc0 >> 1)];
            *(uint4*)dst       = make_uint4(pk[0], pk[1], pk[2], pk[3]);
            *(uint4*)(dst + 4) = make_uint4(pk[4], pk[5], pk[6], pk[7]);
        }
        __syncthreads();

        // ---- mma: 4 k16-steps x 16 n-tiles ----
#pragma unroll
        for (int k = 0; k < 4; k++) {
            int kh = k * 8;
            uint32_t a0 = Ps[(arow0)     * PSW + kh + tID];
            uint32_t a1 = Ps[(arow0 + 8) * PSW + kh + tID];
            uint32_t a2 = Ps[(arow0)     * PSW + kh + tID + 4];
            uint32_t a3 = Ps[(arow0 + 8) * PSW + kh + tID + 4];
#pragma unroll
            for (int n = 0; n < 16; n++) {
                int n0 = nhalf * 128 + n * 8 + gID;
                uint32_t b0 = WhTs[n0 * WTW + kh + tID];
                uint32_t b1 = WhTs[n0 * WTW + kh + tID + 4];
                mma_f16(acc[n], a0, a1, a2, a3, b0, b1);
            }
        }
        __syncthreads();
    }

    // ---- row sums (4 threads share a row) ----
    ssum += __shfl_xor_sync(0xffffffffu, ssum, 1);
    ssum += __shfl_xor_sync(0xffffffffu, ssum, 2);
    if ((t & 3) == 0)
        d_spart[(size_t)split * Nn + i0 + prow] = ssum;

    // ---- store accumulators ----
    float* ap = &d_accpart[((size_t)split * Nn + i0) * FOUT];
    int r0 = mstrip * 16 + gID;
    int cb = nhalf * 128 + tID * 2;
#pragma unroll
    for (int n = 0; n < 16; n++) {
        *(float2*)&ap[(size_t)r0 * FOUT + cb + n * 8] =
            make_float2(acc[n][0], acc[n][1]);
        *(float2*)&ap[(size_t)(r0 + 8) * FOUT + cb + n * 8] =
            make_float2(acc[n][2], acc[n][3]);
    }
}

// ---------------- combine splits, normalize, ELU ----------------
__global__ void combine_kernel(float* __restrict__ out) {
    int i = blockIdx.x, c = threadIdx.x;
    float s = d_spart[i] + d_spart[Nn + i];
    float v = d_accpart[(size_t)i * FOUT + c] +
              d_accpart[(size_t)Nn * FOUT + (size_t)i * FOUT + c];
    float x = v / s;
    out[(size_t)i * FOUT + c] = x > 0.f ? x : expm1f(x);
}

extern "C" void kernel_launch(void* const* d_in, const int* in_sizes, int n_in,
                              void* d_out, int out_size) {
    const float* h   = (const float*)d_in[0];
    const int*   adj = (const int*)d_in[1];
    const float* W   = (const float*)d_in[2];
    const float* a   = (const float*)d_in[3];
    float* out = (float*)d_out;

    cudaFuncSetAttribute(attn_mma, cudaFuncAttributeMaxDynamicSharedMemorySize, SMEM_DYN);

    dim3 g1(Nn / 64, FOUT / 64);
    gemm_wh<<<g1, 256>>>(h, W);
    dim3 gt(Nn / 32, FOUT / 32);
    whconv<<<gt, 256>>>();
    f12_kernel<<<Nn / 8, 256>>>(a);
    pexp_kernel<<<Nn / 256, 256>>>();
    dim3 g3(Nn / M_TILE, NSPLIT);
    attn_mma<<<g3, 512, SMEM_DYN>>>(adj);
    combine_kernel<<<Nn, 256>>>(out);
}

// round 7
// speedup vs baseline: 1.1859x; 1.1859x over previous
#include <cuda_runtime.h>
#include <cuda_bf16.h>
#include <cstdint>

#define Nn     8192
#define FIN    512
#define FOUT   256
#define LALPHA 0.2f
#define NSPLIT 2
#define M_TILE 128
#define KC     64
#define JHALF  (Nn / NSPLIT)      // 4096
#define NCHUNK (JHALF / KC)       // 64

#define WS_STRIDE 264             // Wh tile row stride (words)
#define PS_STRIDE 68              // P tile row stride (words)
#define WHTILE_WORDS (KC * WS_STRIDE)          // 16896
#define SM_PS   (2 * WHTILE_WORDS)             // 33792
#define SM_F2   (SM_PS + M_TILE * PS_STRIDE)   // 42496
#define SM_BB   (SM_F2 + JHALF)                // 46592
#define SM_DD   (SM_BB + JHALF)                // 50688
#define SMEM_DYN ((SM_DD + JHALF) * 4)         // 219136 B

// ---------------- scratch (device globals: allowed) ----------------
__device__ float d_Wh[(size_t)Nn * FOUT];            // 8 MB fp32
__device__ float d_Whr[(size_t)Nn * FOUT];           // 8 MB tf32-rounded
__device__ float d_f1[Nn];
__device__ float d_f2[Nn];
__device__ float d_A[Nn];
__device__ float d_C[Nn];
__device__ float d_B[Nn];
__device__ float d_D[Nn];
__device__ int   d_gmaxkey;
__device__ float d_accpart[(size_t)NSPLIT * Nn * FOUT];  // 16 MB
__device__ float d_spart[(size_t)NSPLIT * Nn];

__device__ __forceinline__ uint32_t tf32_bits(float x) {
    uint32_t r; asm("cvt.rna.tf32.f32 %0, %1;" : "=r"(r) : "f"(x)); return r;
}
__device__ __forceinline__ void mma_tf32(float* d, uint32_t a0, uint32_t a1,
                                         uint32_t a2, uint32_t a3,
                                         uint32_t b0, uint32_t b1) {
    asm volatile(
        "mma.sync.aligned.m16n8k8.row.col.f32.tf32.tf32.f32 "
        "{%0,%1,%2,%3}, {%4,%5,%6,%7}, {%8,%9}, {%0,%1,%2,%3};"
        : "+f"(d[0]), "+f"(d[1]), "+f"(d[2]), "+f"(d[3])
        : "r"(a0), "r"(a1), "r"(a2), "r"(a3), "r"(b0), "r"(b1));
}
__device__ __forceinline__ uint32_t smem_u32(const void* p) {
    uint32_t a;
    asm("{ .reg .u64 t; cvta.to.shared.u64 t, %1; cvt.u32.u64 %0, t; }"
        : "=r"(a) : "l"(p));
    return a;
}
__device__ __forceinline__ void cp_async16(uint32_t sa, const void* g) {
    asm volatile("cp.async.ca.shared.global [%0], [%1], 16;" :: "r"(sa), "l"(g) : "memory");
}
__device__ __forceinline__ void cp_commit() {
    asm volatile("cp.async.commit_group;" ::: "memory");
}
template <int N> __device__ __forceinline__ void cp_wait() {
    asm volatile("cp.async.wait_group %0;" :: "n"(N) : "memory");
}

__device__ __forceinline__ void stage_wh(uint32_t sbase, int bufw, int jg, int t) {
#pragma unroll
    for (int u = 0; u < 8; u++) {
        int f = u * 512 + t;
        int row = f >> 6, c4 = (f & 63) << 2;
        uint32_t sa = sbase + (uint32_t)((bufw + row * WS_STRIDE + c4) * 4);
        cp_async16(sa, &d_Whr[(size_t)(jg + row) * FOUT + c4]);
    }
}

// ---------------- init ----------------
__global__ void init_kernel() { d_gmaxkey = (int)0x80000000; }

// ---------------- Wh = h @ W (also emits tf32-rounded copy) ----------------
__global__ void gemm_wh(const float* __restrict__ h, const float* __restrict__ W) {
    __shared__ float As[16][64];
    __shared__ float Bs[16][64];
    int t  = threadIdx.x;
    int bm = blockIdx.x * 64, bn = blockIdx.y * 64;
    int r0 = (t >> 4) * 4, c0 = (t & 15) * 4;
    int arow = t >> 2, akq = (t & 3) * 4;
    int bkk = t >> 4, bn4 = (t & 15) * 4;

    float acc[4][4];
#pragma unroll
    for (int i = 0; i < 4; i++)
#pragma unroll
        for (int j = 0; j < 4; j++) acc[i][j] = 0.f;

    for (int k0 = 0; k0 < FIN; k0 += 16) {
        float4 av = *(const float4*)&h[(size_t)(bm + arow) * FIN + k0 + akq];
        As[akq + 0][arow] = av.x; As[akq + 1][arow] = av.y;
        As[akq + 2][arow] = av.z; As[akq + 3][arow] = av.w;
        *(float4*)&Bs[bkk][bn4] = *(const float4*)&W[(size_t)(k0 + bkk) * FOUT + bn + bn4];
        __syncthreads();
#pragma unroll
        for (int kk = 0; kk < 16; kk++) {
            float4 a4 = *(float4*)&As[kk][r0];
            float4 b4 = *(float4*)&Bs[kk][c0];
            acc[0][0] += a4.x * b4.x; acc[0][1] += a4.x * b4.y;
            acc[0][2] += a4.x * b4.z; acc[0][3] += a4.x * b4.w;
            acc[1][0] += a4.y * b4.x; acc[1][1] += a4.y * b4.y;
            acc[1][2] += a4.y * b4.z; acc[1][3] += a4.y * b4.w;
            acc[2][0] += a4.z * b4.x; acc[2][1] += a4.z * b4.y;
            acc[2][2] += a4.z * b4.z; acc[2][3] += a4.z * b4.w;
            acc[3][0] += a4.w * b4.x; acc[3][1] += a4.w * b4.y;
            acc[3][2] += a4.w * b4.z; acc[3][3] += a4.w * b4.w;
        }
        __syncthreads();
    }
#pragma unroll
    for (int i = 0; i < 4; i++) {
        size_t off = (size_t)(bm + r0 + i) * FOUT + bn + c0;
        *(float4*)&d_Wh[off] =
            make_float4(acc[i][0], acc[i][1], acc[i][2], acc[i][3]);
        float4 rr;
        rr.x = __uint_as_float(tf32_bits(acc[i][0]));
        rr.y = __uint_as_float(tf32_bits(acc[i][1]));
        rr.z = __uint_as_float(tf32_bits(acc[i][2]));
        rr.w = __uint_as_float(tf32_bits(acc[i][3]));
        *(float4*)&d_Whr[off] = rr;
    }
}

// ---------------- f1, f2 and global max(f2) ----------------
__global__ void f12_kernel(const float* __restrict__ a) {
    int lane = threadIdx.x & 31, warp = threadIdx.x >> 5;
    int row  = blockIdx.x * 8 + warp;
    const float* wr = &d_Wh[(size_t)row * FOUT];
    float s1 = 0.f, s2 = 0.f;
#pragma unroll
    for (int q = 0; q < 2; q++) {
        int c = q * 128 + lane * 4;
        float4 v  = *(const float4*)&wr[c];
        float4 a1 = *(const float4*)&a[c];
        float4 a2 = *(const float4*)&a[FOUT + c];
        s1 += v.x * a1.x + v.y * a1.y + v.z * a1.z + v.w * a1.w;
        s2 += v.x * a2.x + v.y * a2.y + v.z * a2.z + v.w * a2.w;
    }
#pragma unroll
    for (int o = 16; o; o >>= 1) {
        s1 += __shfl_xor_sync(0xffffffffu, s1, o);
        s2 += __shfl_xor_sync(0xffffffffu, s2, o);
    }
    if (lane == 0) {
        d_f1[row] = s1;
        d_f2[row] = s2;
        int b   = __float_as_int(s2);
        int key = b >= 0 ? b : (b ^ 0x7fffffff);
        atomicMax(&d_gmaxkey, key);
    }
}

// ---------------- factorized softmax weights (split into 2 launches) ----------------
__global__ void pexpAC_kernel() {
    int i = blockIdx.x * 256 + threadIdx.x;
    int kk = d_gmaxkey;
    float gm = __int_as_float(kk >= 0 ? kk : (kk ^ 0x7fffffff));
    float u  = d_f1[i] + gm;
    float m  = u > 0.f ? u : LALPHA * u;
    d_A[i] = __expf(u - m);
    d_C[i] = __expf(LALPHA * u - m);
}
__global__ void pexpBD_kernel() {
    int i = blockIdx.x * 256 + threadIdx.x;
    int kk = d_gmaxkey;
    float gm = __int_as_float(kk >= 0 ? kk : (kk ^ 0x7fffffff));
    float v = d_f2[i] - gm;
    d_B[i] = __expf(v);
    d_D[i] = __expf(LALPHA * v);
}

// ---------------- fused attention @ Wh via mma.sync tf32 (pipelined) ----------------
__global__ void __launch_bounds__(512, 1) attn_mma(const int* __restrict__ adj) {
    extern __shared__ float sm[];
    uint32_t* Ps  = (uint32_t*)(sm + SM_PS);
    float*    f2s = sm + SM_F2;
    float*    Bss = sm + SM_BB;
    float*    Dss = sm + SM_DD;
    uint32_t sbase = smem_u32(sm);

    int t    = threadIdx.x;
    int lane = t & 31, wid = t >> 5;
    int mstrip = wid >> 1, nhalf = wid & 1;
    int i0    = blockIdx.x * M_TILE;
    int split = blockIdx.y;
    int jbeg  = split * JHALF;

    int prow = t >> 2;
    int pc0  = (t & 3) << 4;
    float f1r = d_f1[i0 + prow];
    float Ar  = d_A[i0 + prow];
    float Cr  = d_C[i0 + prow];
    const int4* adjrow = (const int4*)(adj + (size_t)(i0 + prow) * Nn);
    float ssum = 0.f;

    // stage chunk 0 (cp.async)
    stage_wh(sbase, 0, jbeg, t);
    cp_commit();

    // fill f2/B/D smem for the whole j-half
#pragma unroll
    for (int u = 0; u < 2; u++) {
        int idx = (u * 512 + t) * 4;
        *(float4*)&f2s[idx] = *(const float4*)&d_f2[jbeg + idx];
        *(float4*)&Bss[idx] = *(const float4*)&d_B[jbeg + idx];
        *(float4*)&Dss[idx] = *(const float4*)&d_D[jbeg + idx];
    }

    // adj prefetch chunk 0
    int4 adp0, adp1, adp2, adp3;
    {
        int base = (jbeg + pc0) >> 2;
        adp0 = adjrow[base];     adp1 = adjrow[base + 1];
        adp2 = adjrow[base + 2]; adp3 = adjrow[base + 3];
    }

    float acc[16][4];
#pragma unroll
    for (int n = 0; n < 16; n++)
#pragma unroll
        for (int u = 0; u < 4; u++) acc[n][u] = 0.f;

    int gID = lane >> 2, tID = lane & 3;
    int arow0 = mstrip * 16 + gID;

    __syncthreads();   // f2/B/D fill visible

    for (int c = 0; c < NCHUNK; c++) {
        int buf = c & 1;
        int jl  = c * KC;

        // issue next chunk's Wh staging early (overlaps P + MMA)
        if (c + 1 < NCHUNK) {
            stage_wh(sbase, ((c + 1) & 1) * WHTILE_WORDS, jbeg + jl + KC, t);
            cp_commit();
        }

        // ---- P tile from prefetched adj + smem f2/B/D ----
        int4 adv[4] = {adp0, adp1, adp2, adp3};
#pragma unroll
        for (int u = 0; u < 4; u++) {
            int cc = pc0 + u * 4;
            int4   ad  = adv[u];
            float4 f2v = *(float4*)&f2s[jl + cc];
            float4 Bv  = *(float4*)&Bss[jl + cc];
            float4 Dv  = *(float4*)&Dss[jl + cc];
            float s0 = f1r + f2v.x, s1 = f1r + f2v.y;
            float s2 = f1r + f2v.z, s3 = f1r + f2v.w;
            float p0 = (ad.x > 0) ? (s0 > 0.f ? Ar * Bv.x : Cr * Dv.x) : 0.f;
            float p1 = (ad.y > 0) ? (s1 > 0.f ? Ar * Bv.y : Cr * Dv.y) : 0.f;
            float p2 = (ad.z > 0) ? (s2 > 0.f ? Ar * Bv.z : Cr * Dv.z) : 0.f;
            float p3 = (ad.w > 0) ? (s3 > 0.f ? Ar * Bv.w : Cr * Dv.w) : 0.f;
            ssum += (p0 + p1) + (p2 + p3);
            uint4 q = make_uint4(tf32_bits(p0), tf32_bits(p1),
                                 tf32_bits(p2), tf32_bits(p3));
            *(uint4*)&Ps[prow * PS_STRIDE + cc] = q;
        }

        // ---- prefetch adj for next chunk (hidden behind MMA) ----
        if (c + 1 < NCHUNK) {
            int base = (jbeg + jl + KC + pc0) >> 2;
            adp0 = adjrow[base];     adp1 = adjrow[base + 1];
            adp2 = adjrow[base + 2]; adp3 = adjrow[base + 3];
        }

        if (c + 1 < NCHUNK) cp_wait<1>(); else cp_wait<0>();
        __syncthreads();

        // ---- mma: 8 k-steps x 16 n-tiles ----
        const float* Wb = sm + buf * WHTILE_WORDS;
#pragma unroll
        for (int k = 0; k < 8; k++) {
            int kc = tID + 8 * k;
            uint32_t a0 = Ps[(arow0)     * PS_STRIDE + kc];
            uint32_t a1 = Ps[(arow0 + 8) * PS_STRIDE + kc];
            uint32_t a2 = Ps[(arow0)     * PS_STRIDE + kc + 4];
            uint32_t a3 = Ps[(arow0 + 8) * PS_STRIDE + kc + 4];
            int krow = k * 8 + tID;
#pragma unroll
            for (int n = 0; n < 16; n++) {
                int n0 = nhalf * 128 + n * 8 + gID;
                uint32_t b0 = __float_as_uint(Wb[krow * WS_STRIDE + n0]);
                uint32_t b1 = __float_as_uint(Wb[(krow + 4) * WS_STRIDE + n0]);
                mma_tf32(acc[n], a0, a1, a2, a3, b0, b1);
            }
        }
        __syncthreads();
    }

    // ---- row sums (4 threads share a row) ----
    ssum += __shfl_xor_sync(0xffffffffu, ssum, 1);
    ssum += __shfl_xor_sync(0xffffffffu, ssum, 2);
    if ((t & 3) == 0)
        d_spart[(size_t)split * Nn + i0 + prow] = ssum;

    // ---- store accumulators ----
    float* ap = &d_accpart[((size_t)split * Nn + i0) * FOUT];
    int r0 = mstrip * 16 + gID;
    int cb = nhalf * 128 + tID * 2;
#pragma unroll
    for (int n = 0; n < 16; n++) {
        *(float2*)&ap[(size_t)r0 * FOUT + cb + n * 8] =
            make_float2(acc[n][0], acc[n][1]);
        *(float2*)&ap[(size_t)(r0 + 8) * FOUT + cb + n * 8] =
            make_float2(acc[n][2], acc[n][3]);
    }
}

// ---------------- combine splits, normalize, ELU ----------------
__global__ void combine_kernel(float* __restrict__ out) {
    int i = blockIdx.x, c = threadIdx.x;
    float s = d_spart[i] + d_spart[Nn + i];
    float v = d_accpart[(size_t)i * FOUT + c] +
              d_accpart[(size_t)Nn * FOUT + (size_t)i * FOUT + c];
    float x = v / s;
    out[(size_t)i * FOUT + c] = x > 0.f ? x : expm1f(x);
}

extern "C" void kernel_launch(void* const* d_in, const int* in_sizes, int n_in,
                              void* d_out, int out_size) {
    const float* h   = (const float*)d_in[0];
    const int*   adj = (const int*)d_in[1];
    const float* W   = (const float*)d_in[2];
    const float* a   = (const float*)d_in[3];
    float* out = (float*)d_out;

    cudaFuncSetAttribute(attn_mma, cudaFuncAttributeMaxDynamicSharedMemorySize, SMEM_DYN);

    init_kernel<<<1, 1>>>();                       // launch 1
    dim3 g1(Nn / 64, FOUT / 64);
    gemm_wh<<<g1, 256>>>(h, W);                    // launch 2
    f12_kernel<<<Nn / 8, 256>>>(a);                // launch 3
    pexpAC_kernel<<<Nn / 256, 256>>>();            // launch 4
    pexpBD_kernel<<<Nn / 256, 256>>>();            // launch 5
    dim3 g3(Nn / M_TILE, NSPLIT);
    attn_mma<<<g3, 512, SMEM_DYN>>>(adj);          // launch 6 (ncu -s 5 lands here)
    combine_kernel<<<Nn, 256>>>(out);              // launch 7
}

// round 8
// speedup vs baseline: 1.6080x; 1.3560x over previous
#include <cuda_runtime.h>
#include <cuda_bf16.h>
#include <cstdint>

#define Nn     8192
#define FIN    512
#define FOUT   256
#define LALPHA 0.2f
#define M_TILE 128
#define KC     64
#define NBLK   (Nn / M_TILE)          // 64 row blocks
#define CPB    (Nn / KC)              // 128 chunks per row block
#define TOTSLOT (NBLK * CPB)          // 8192
#define NCTA   148

#define WS_STRIDE 264                 // Wh tile row stride (words)
#define ADJ_STRIDE 68                 // adj tile row stride (words)
#define WHTILE_WORDS (KC * WS_STRIDE)         // 16896
#define ADJTILE_WORDS (M_TILE * ADJ_STRIDE)   // 8704
#define SM_ADJ (2 * WHTILE_WORDS)             // 33792
#define SM_FBD (SM_ADJ + 2 * ADJTILE_WORDS)   // 51200
#define SMEM_DYN ((SM_FBD + 2 * 192) * 4)     // 206336 B

// ---------------- scratch (device globals: allowed) ----------------
__device__ float d_Wh[(size_t)Nn * FOUT];            // 8 MB fp32
__device__ float d_Whr[(size_t)Nn * FOUT];           // 8 MB tf32-rounded
__device__ float d_f1[Nn];
__device__ float d_f2[Nn];
__device__ float d_A[Nn];
__device__ float d_C[Nn];
__device__ float d_B[Nn];
__device__ float d_D[Nn];
__device__ int   d_gmaxkey;
__device__ float d_num[(size_t)Nn * FOUT];           // 8 MB (atomic accum)
__device__ float d_ssum[Nn];

__device__ __forceinline__ uint32_t tf32_bits(float x) {
    uint32_t r; asm("cvt.rna.tf32.f32 %0, %1;" : "=r"(r) : "f"(x)); return r;
}
__device__ __forceinline__ void mma_tf32(float* d, uint32_t a0, uint32_t a1,
                                         uint32_t a2, uint32_t a3,
                                         uint32_t b0, uint32_t b1) {
    asm volatile(
        "mma.sync.aligned.m16n8k8.row.col.f32.tf32.tf32.f32 "
        "{%0,%1,%2,%3}, {%4,%5,%6,%7}, {%8,%9}, {%0,%1,%2,%3};"
        : "+f"(d[0]), "+f"(d[1]), "+f"(d[2]), "+f"(d[3])
        : "r"(a0), "r"(a1), "r"(a2), "r"(a3), "r"(b0), "r"(b1));
}
__device__ __forceinline__ uint32_t smem_u32(const void* p) {
    uint32_t a;
    asm("{ .reg .u64 t; cvta.to.shared.u64 t, %1; cvt.u32.u64 %0, t; }"
        : "=r"(a) : "l"(p));
    return a;
}
__device__ __forceinline__ void cp_async16(uint32_t sa, const void* g) {
    asm volatile("cp.async.ca.shared.global [%0], [%1], 16;" :: "r"(sa), "l"(g) : "memory");
}
__device__ __forceinline__ void cp_commit() {
    asm volatile("cp.async.commit_group;" ::: "memory");
}
template <int N> __device__ __forceinline__ void cp_wait() {
    asm volatile("cp.async.wait_group %0;" :: "n"(N) : "memory");
}

// ---------------- zero / init ----------------
__global__ void zero_kernel() {
    if (blockIdx.x == 0 && threadIdx.x == 0) d_gmaxkey = (int)0x80000000;
    size_t i = ((size_t)blockIdx.x * 256 + threadIdx.x) * 4;
    if (i < (size_t)Nn * FOUT)
        *(float4*)&d_num[i] = make_float4(0.f, 0.f, 0.f, 0.f);
    if (i < Nn)
        *(float4*)&d_ssum[i] = make_float4(0.f, 0.f, 0.f, 0.f);
}

// ---------------- Wh = h @ W (emits fp32 + tf32-rounded) ----------------
__global__ void gemm_wh(const float* __restrict__ h, const float* __restrict__ W) {
    __shared__ float As[16][64];
    __shared__ float Bs[16][64];
    int t  = threadIdx.x;
    int bm = blockIdx.x * 64, bn = blockIdx.y * 64;
    int r0 = (t >> 4) * 4, c0 = (t & 15) * 4;
    int arow = t >> 2, akq = (t & 3) * 4;
    int bkk = t >> 4, bn4 = (t & 15) * 4;

    float acc[4][4];
#pragma unroll
    for (int i = 0; i < 4; i++)
#pragma unroll
        for (int j = 0; j < 4; j++) acc[i][j] = 0.f;

    for (int k0 = 0; k0 < FIN; k0 += 16) {
        float4 av = *(const float4*)&h[(size_t)(bm + arow) * FIN + k0 + akq];
        As[akq + 0][arow] = av.x; As[akq + 1][arow] = av.y;
        As[akq + 2][arow] = av.z; As[akq + 3][arow] = av.w;
        *(float4*)&Bs[bkk][bn4] = *(const float4*)&W[(size_t)(k0 + bkk) * FOUT + bn + bn4];
        __syncthreads();
#pragma unroll
        for (int kk = 0; kk < 16; kk++) {
            float4 a4 = *(float4*)&As[kk][r0];
            float4 b4 = *(float4*)&Bs[kk][c0];
            acc[0][0] += a4.x * b4.x; acc[0][1] += a4.x * b4.y;
            acc[0][2] += a4.x * b4.z; acc[0][3] += a4.x * b4.w;
            acc[1][0] += a4.y * b4.x; acc[1][1] += a4.y * b4.y;
            acc[1][2] += a4.y * b4.z; acc[1][3] += a4.y * b4.w;
            acc[2][0] += a4.z * b4.x; acc[2][1] += a4.z * b4.y;
            acc[2][2] += a4.z * b4.z; acc[2][3] += a4.z * b4.w;
            acc[3][0] += a4.w * b4.x; acc[3][1] += a4.w * b4.y;
            acc[3][2] += a4.w * b4.z; acc[3][3] += a4.w * b4.w;
        }
        __syncthreads();
    }
#pragma unroll
    for (int i = 0; i < 4; i++) {
        size_t off = (size_t)(bm + r0 + i) * FOUT + bn + c0;
        *(float4*)&d_Wh[off] =
            make_float4(acc[i][0], acc[i][1], acc[i][2], acc[i][3]);
        float4 rr;
        rr.x = __uint_as_float(tf32_bits(acc[i][0]));
        rr.y = __uint_as_float(tf32_bits(acc[i][1]));
        rr.z = __uint_as_float(tf32_bits(acc[i][2]));
        rr.w = __uint_as_float(tf32_bits(acc[i][3]));
        *(float4*)&d_Whr[off] = rr;
    }
}

// ---------------- f1, f2 and global max(f2) ----------------
__global__ void f12_kernel(const float* __restrict__ a) {
    int lane = threadIdx.x & 31, warp = threadIdx.x >> 5;
    int row  = blockIdx.x * 8 + warp;
    const float* wr = &d_Wh[(size_t)row * FOUT];
    float s1 = 0.f, s2 = 0.f;
#pragma unroll
    for (int q = 0; q < 2; q++) {
        int c = q * 128 + lane * 4;
        float4 v  = *(const float4*)&wr[c];
        float4 a1 = *(const float4*)&a[c];
        float4 a2 = *(const float4*)&a[FOUT + c];
        s1 += v.x * a1.x + v.y * a1.y + v.z * a1.z + v.w * a1.w;
        s2 += v.x * a2.x + v.y * a2.y + v.z * a2.z + v.w * a2.w;
    }
#pragma unroll
    for (int o = 16; o; o >>= 1) {
        s1 += __shfl_xor_sync(0xffffffffu, s1, o);
        s2 += __shfl_xor_sync(0xffffffffu, s2, o);
    }
    if (lane == 0) {
        d_f1[row] = s1;
        d_f2[row] = s2;
        int b   = __float_as_int(s2);
        int key = b >= 0 ? b : (b ^ 0x7fffffff);
        atomicMax(&d_gmaxkey, key);
    }
}

// ---------------- factorized softmax weights ----------------
__global__ void pexp_kernel() {
    int i = blockIdx.x * 256 + threadIdx.x;
    int kk = d_gmaxkey;
    float gm = __int_as_float(kk >= 0 ? kk : (kk ^ 0x7fffffff));
    float f1 = d_f1[i], f2 = d_f2[i];
    float u  = f1 + gm;
    float m  = u > 0.f ? u : LALPHA * u;
    d_A[i] = __expf(u - m);
    d_C[i] = __expf(LALPHA * u - m);
    float v = f2 - gm;
    d_B[i] = __expf(v);
    d_D[i] = __expf(LALPHA * v);
}

// ---------------- staging helpers (cp.async) ----------------
__device__ __forceinline__ void stage_slot(uint32_t sbase, const int* adj,
                                           int s, int t) {
    int buf = s & 1;
    int ib  = s >> 7;
    int jg  = (s & (CPB - 1)) * KC;
    // Wh tile [64][256] -> stride 264
    uint32_t wb = sbase + (uint32_t)(buf * WHTILE_WORDS * 4);
#pragma unroll
    for (int u = 0; u < 8; u++) {
        int f = u * 512 + t;
        int row = f >> 6, c4 = (f & 63) << 2;
        cp_async16(wb + (uint32_t)((row * WS_STRIDE + c4) * 4),
                   &d_Whr[(size_t)(jg + row) * FOUT + c4]);
    }
    // adj tile [128][64] -> stride 68
    uint32_t ab = sbase + (uint32_t)((SM_ADJ + buf * ADJTILE_WORDS) * 4);
    const int* abase = adj + (size_t)ib * M_TILE * Nn + jg;
#pragma unroll
    for (int u = 0; u < 4; u++) {
        int f = u * 512 + t;
        int row = f >> 4, seg = (f & 15) << 2;
        cp_async16(ab + (uint32_t)((row * ADJ_STRIDE + seg) * 4),
                   abase + (size_t)row * Nn + seg);
    }
    // f2/B/D: 48 x 16B
    if (t < 48) {
        uint32_t fb = sbase + (uint32_t)((SM_FBD + buf * 192 + t * 4) * 4);
        const float* src = (t < 16) ? &d_f2[jg + t * 4]
                         : (t < 32) ? &d_B[jg + (t - 16) * 4]
                                    : &d_D[jg + (t - 32) * 4];
        cp_async16(fb, src);
    }
}

// ---------------- fused attention @ Wh via mma.sync tf32 ----------------
// 148 CTAs x 512 threads. Slots = (row_block, 64-j chunk); each CTA takes a
// contiguous slot range (<=2 row blocks). P computed inline in registers.
__global__ void __launch_bounds__(512, 1) attn_mma(const int* __restrict__ adj) {
    extern __shared__ float sm[];
    uint32_t sbase = smem_u32(sm);

    int t    = threadIdx.x;
    int lane = t & 31, wid = t >> 5;
    int mstrip = wid >> 1, nhalf = wid & 1;
    int gID = lane >> 2, tID = lane & 3;
    int r0t = mstrip * 16 + gID;          // tile row (second row = +8)

    int s0 = (int)(((long long)blockIdx.x * TOTSLOT) / NCTA);
    int s1 = (int)(((long long)(blockIdx.x + 1) * TOTSLOT) / NCTA);

    float acc[16][4];
#pragma unroll
    for (int n = 0; n < 16; n++)
#pragma unroll
        for (int u = 0; u < 4; u++) acc[n][u] = 0.f;
    float ssum0 = 0.f, ssum1 = 0.f;

    float f1a = 0.f, Aa = 0.f, Ca = 0.f;   // row r0t consts
    float f1b = 0.f, Ab = 0.f, Cb = 0.f;   // row r0t+8 consts
    int cur_ib = -1;

    stage_slot(sbase, adj, s0, t);
    cp_commit();

    for (int s = s0; s < s1; s++) {
        int ib = s >> 7;
        int buf = s & 1;

        if (ib != cur_ib) {
            if (cur_ib >= 0) {
                // flush partials for cur_ib
                float sa = ssum0 + __shfl_xor_sync(0xffffffffu, ssum0, 1);
                sa += __shfl_xor_sync(0xffffffffu, sa, 2);
                float sb = ssum1 + __shfl_xor_sync(0xffffffffu, ssum1, 1);
                sb += __shfl_xor_sync(0xffffffffu, sb, 2);
                int base = cur_ib * M_TILE;
                if (tID == 0 && nhalf == 0) {
                    atomicAdd(&d_ssum[base + r0t], sa);
                    atomicAdd(&d_ssum[base + r0t + 8], sb);
                }
                float* np = &d_num[(size_t)(base) * FOUT];
                int cb = nhalf * 128 + tID * 2;
#pragma unroll
                for (int n = 0; n < 16; n++) {
                    int cc = cb + n * 8;
                    atomicAdd(&np[(size_t)r0t * FOUT + cc],       acc[n][0]);
                    atomicAdd(&np[(size_t)r0t * FOUT + cc + 1],   acc[n][1]);
                    atomicAdd(&np[(size_t)(r0t + 8) * FOUT + cc],     acc[n][2]);
                    atomicAdd(&np[(size_t)(r0t + 8) * FOUT + cc + 1], acc[n][3]);
                }
#pragma unroll
                for (int n = 0; n < 16; n++)
#pragma unroll
                    for (int u = 0; u < 4; u++) acc[n][u] = 0.f;
                ssum0 = 0.f; ssum1 = 0.f;
            }
            int base = ib * M_TILE;
            f1a = d_f1[base + r0t];     f1b = d_f1[base + r0t + 8];
            Aa  = d_A[base + r0t];      Ab  = d_A[base + r0t + 8];
            Ca  = d_C[base + r0t];      Cb  = d_C[base + r0t + 8];
            cur_ib = ib;
        }

        cp_wait<0>();
        __syncthreads();     // buffers(s) visible; MMA(s-1) retired by all warps

        if (s + 1 < s1) {
            stage_slot(sbase, adj, s + 1, t);
            cp_commit();
        }

        const float* Wb   = sm + buf * WHTILE_WORDS;
        const int*   adjS = (const int*)(sm + SM_ADJ + buf * ADJTILE_WORDS);
        const float* fbd  = sm + SM_FBD + buf * 192;

#pragma unroll
        for (int k = 0; k < 8; k++) {
            int j0 = tID + 8 * k, j1 = j0 + 4;
            int ad00 = adjS[r0t * ADJ_STRIDE + j0];
            int ad10 = adjS[(r0t + 8) * ADJ_STRIDE + j0];
            int ad01 = adjS[r0t * ADJ_STRIDE + j1];
            int ad11 = adjS[(r0t + 8) * ADJ_STRIDE + j1];
            float f20 = fbd[j0], B0 = fbd[64 + j0], D0 = fbd[128 + j0];
            float f21 = fbd[j1], B1 = fbd[64 + j1], D1 = fbd[128 + j1];
            float e00 = f1a + f20, e10 = f1b + f20;
            float e01 = f1a + f21, e11 = f1b + f21;
            float p00 = (ad00 > 0) ? (e00 > 0.f ? Aa * B0 : Ca * D0) : 0.f;
            float p10 = (ad10 > 0) ? (e10 > 0.f ? Ab * B0 : Cb * D0) : 0.f;
            float p01 = (ad01 > 0) ? (e01 > 0.f ? Aa * B1 : Ca * D1) : 0.f;
            float p11 = (ad11 > 0) ? (e11 > 0.f ? Ab * B1 : Cb * D1) : 0.f;
            if (nhalf == 0) { ssum0 += p00 + p01; ssum1 += p10 + p11; }
            uint32_t a0 = tf32_bits(p00), a1 = tf32_bits(p10);
            uint32_t a2 = tf32_bits(p01), a3 = tf32_bits(p11);
            int krow = k * 8 + tID;
#pragma unroll
            for (int n = 0; n < 16; n++) {
                int n0 = nhalf * 128 + n * 8 + gID;
                uint32_t b0 = __float_as_uint(Wb[krow * WS_STRIDE + n0]);
                uint32_t b1 = __float_as_uint(Wb[(krow + 4) * WS_STRIDE + n0]);
                mma_tf32(acc[n], a0, a1, a2, a3, b0, b1);
            }
        }
    }

    // final flush
    {
        float sa = ssum0 + __shfl_xor_sync(0xffffffffu, ssum0, 1);
        sa += __shfl_xor_sync(0xffffffffu, sa, 2);
        float sb = ssum1 + __shfl_xor_sync(0xffffffffu, ssum1, 1);
        sb += __shfl_xor_sync(0xffffffffu, sb, 2);
        int base = cur_ib * M_TILE;
        if (tID == 0 && nhalf == 0) {
            atomicAdd(&d_ssum[base + r0t], sa);
            atomicAdd(&d_ssum[base + r0t + 8], sb);
        }
        float* np = &d_num[(size_t)(base) * FOUT];
        int cb = nhalf * 128 + tID * 2;
#pragma unroll
        for (int n = 0; n < 16; n++) {
            int cc = cb + n * 8;
            atomicAdd(&np[(size_t)r0t * FOUT + cc],       acc[n][0]);
            atomicAdd(&np[(size_t)r0t * FOUT + cc + 1],   acc[n][1]);
            atomicAdd(&np[(size_t)(r0t + 8) * FOUT + cc],     acc[n][2]);
            atomicAdd(&np[(size_t)(r0t + 8) * FOUT + cc + 1], acc[n][3]);
        }
    }
}

// ---------------- normalize + ELU ----------------
__global__ void elu_kernel(float* __restrict__ out) {
    int i = blockIdx.x, c = threadIdx.x;
    float x = d_num[(size_t)i * FOUT + c] / d_ssum[i];
    out[(size_t)i * FOUT + c] = x > 0.f ? x : expm1f(x);
}

extern "C" void kernel_launch(void* const* d_in, const int* in_sizes, int n_in,
                              void* d_out, int out_size) {
    const float* h   = (const float*)d_in[0];
    const int*   adj = (const int*)d_in[1];
    const float* W   = (const float*)d_in[2];
    const float* a   = (const float*)d_in[3];
    float* out = (float*)d_out;

    cudaFuncSetAttribute(attn_mma, cudaFuncAttributeMaxDynamicSharedMemorySize, SMEM_DYN);

    zero_kernel<<<(Nn * FOUT) / 1024, 256>>>();
    dim3 g1(Nn / 64, FOUT / 64);
    gemm_wh<<<g1, 256>>>(h, W);
    f12_kernel<<<Nn / 8, 256>>>(a);
    pexp_kernel<<<Nn / 256, 256>>>();
    attn_mma<<<NCTA, 512, SMEM_DYN>>>(adj);
    elu_kernel<<<Nn, 256>>>(out);
}

// round 9
// speedup vs baseline: 1.8682x; 1.1618x over previous
#include <cuda_runtime.h>
#include <cuda_bf16.h>
#include <cstdint>

#define Nn     8192
#define FIN    512
#define FOUT   256
#define LALPHA 0.2f
#define M_TILE 128
#define KC     64
#define NBLK   (Nn / M_TILE)          // 64 row blocks
#define CPB    (Nn / KC)              // 128 chunks per row block
#define TOTSLOT (NBLK * CPB)          // 8192
#define NCTA   148

#define WS_STRIDE 264                 // Wh/W tile row stride (words)
#define ADJ_STRIDE 68                 // adj tile row stride (words)
#define WHTILE_WORDS (KC * WS_STRIDE)         // 16896
#define ADJTILE_WORDS (M_TILE * ADJ_STRIDE)   // 8704
#define SM_ADJ (2 * WHTILE_WORDS)             // 33792
#define SM_FBD (SM_ADJ + 2 * ADJTILE_WORDS)   // 51200
#define SMEM_DYN ((SM_FBD + 2 * 192) * 4)     // 206336 B

// gemm_wh_mma tiles
#define GM      64
#define HS      68
#define HS_WORDS (GM * HS)                    // 4352
#define GSMEM_DYN ((2 * HS_WORDS + 2 * WHTILE_WORDS) * 4)   // 169984 B

// ---------------- scratch (device globals: allowed) ----------------
__device__ float d_Wh[(size_t)Nn * FOUT];            // 8 MB fp32
__device__ float d_Whr[(size_t)Nn * FOUT];           // 8 MB tf32-rounded
__device__ float d_Wr[(size_t)FIN * FOUT];           // 512 KB tf32-rounded W
__device__ float d_f1[Nn];
__device__ float d_f2[Nn];
__device__ float d_A[Nn];
__device__ float d_C[Nn];
__device__ float d_B[Nn];
__device__ float d_D[Nn];
__device__ int   d_gmaxkey;
__device__ float d_num[(size_t)Nn * FOUT];           // 8 MB (atomic accum)
__device__ float d_ssum[Nn];

__device__ __forceinline__ uint32_t tf32_bits(float x) {
    uint32_t r; asm("cvt.rna.tf32.f32 %0, %1;" : "=r"(r) : "f"(x)); return r;
}
__device__ __forceinline__ void mma_tf32(float* d, uint32_t a0, uint32_t a1,
                                         uint32_t a2, uint32_t a3,
                                         uint32_t b0, uint32_t b1) {
    asm volatile(
        "mma.sync.aligned.m16n8k8.row.col.f32.tf32.tf32.f32 "
        "{%0,%1,%2,%3}, {%4,%5,%6,%7}, {%8,%9}, {%0,%1,%2,%3};"
        : "+f"(d[0]), "+f"(d[1]), "+f"(d[2]), "+f"(d[3])
        : "r"(a0), "r"(a1), "r"(a2), "r"(a3), "r"(b0), "r"(b1));
}
__device__ __forceinline__ uint32_t smem_u32(const void* p) {
    uint32_t a;
    asm("{ .reg .u64 t; cvta.to.shared.u64 t, %1; cvt.u32.u64 %0, t; }"
        : "=r"(a) : "l"(p));
    return a;
}
__device__ __forceinline__ void cp_async16(uint32_t sa, const void* g) {
    asm volatile("cp.async.ca.shared.global [%0], [%1], 16;" :: "r"(sa), "l"(g) : "memory");
}
__device__ __forceinline__ void cp_commit() {
    asm volatile("cp.async.commit_group;" ::: "memory");
}
template <int N> __device__ __forceinline__ void cp_wait() {
    asm volatile("cp.async.wait_group %0;" :: "n"(N) : "memory");
}

// ---------------- zero / init ----------------
__global__ void zero_kernel() {
    if (blockIdx.x == 0 && threadIdx.x == 0) d_gmaxkey = (int)0x80000000;
    size_t i = ((size_t)blockIdx.x * 256 + threadIdx.x) * 4;
    if (i < (size_t)Nn * FOUT)
        *(float4*)&d_num[i] = make_float4(0.f, 0.f, 0.f, 0.f);
    if (i < Nn)
        *(float4*)&d_ssum[i] = make_float4(0.f, 0.f, 0.f, 0.f);
}

// ---------------- round W to tf32 ----------------
__global__ void wround_kernel(const float* __restrict__ W) {
    int i = (blockIdx.x * 256 + threadIdx.x) * 4;
    float4 v = *(const float4*)&W[i];
    float4 o;
    o.x = __uint_as_float(tf32_bits(v.x));
    o.y = __uint_as_float(tf32_bits(v.y));
    o.z = __uint_as_float(tf32_bits(v.z));
    o.w = __uint_as_float(tf32_bits(v.w));
    *(float4*)&d_Wr[i] = o;
}

// ---------------- Wh = h @ W via mma.sync tf32 ----------------
// 128 CTAs x 256 threads (8 warps: 4 m-strips x 2 n-halves), CTA tile 64x256,
// K=512 in 8 double-buffered cp.async chunks of 64.
__device__ __forceinline__ void stage_g(uint32_t sbase, const float* __restrict__ h,
                                        int i0, int c, int t) {
    int buf = c & 1;
    int k0  = c * KC;
    uint32_t hb = sbase + (uint32_t)(buf * HS_WORDS * 4);
#pragma unroll
    for (int u = 0; u < 4; u++) {
        int f = u * 256 + t;
        int row = f >> 4, seg = (f & 15) << 2;
        cp_async16(hb + (uint32_t)((row * HS + seg) * 4),
                   &h[(size_t)(i0 + row) * FIN + k0 + seg]);
    }
    uint32_t wb = sbase + (uint32_t)((2 * HS_WORDS + buf * WHTILE_WORDS) * 4);
#pragma unroll
    for (int u = 0; u < 16; u++) {
        int f = u * 256 + t;
        int row = f >> 6, c4 = (f & 63) << 2;
        cp_async16(wb + (uint32_t)((row * WS_STRIDE + c4) * 4),
                   &d_Wr[(size_t)(k0 + row) * FOUT + c4]);
    }
}

__global__ void __launch_bounds__(256, 1) gemm_wh_mma(const float* __restrict__ h) {
    extern __shared__ float gsm[];
    uint32_t sbase = smem_u32(gsm);

    int t    = threadIdx.x;
    int lane = t & 31, wid = t >> 5;
    int mstrip = wid >> 1, nhalf = wid & 1;
    int gID = lane >> 2, tID = lane & 3;
    int r0t = mstrip * 16 + gID;
    int i0  = blockIdx.x * GM;

    float acc[16][4];
#pragma unroll
    for (int n = 0; n < 16; n++)
#pragma unroll
        for (int u = 0; u < 4; u++) acc[n][u] = 0.f;

    stage_g(sbase, h, i0, 0, t);
    cp_commit();

    for (int c = 0; c < FIN / KC; c++) {
        int buf = c & 1;
        cp_wait<0>();
        __syncthreads();
        if (c + 1 < FIN / KC) {
            stage_g(sbase, h, i0, c + 1, t);
            cp_commit();
        }
        const float* hs = gsm + buf * HS_WORDS;
        const float* Wb = gsm + 2 * HS_WORDS + buf * WHTILE_WORDS;
#pragma unroll
        for (int k = 0; k < 8; k++) {
            int kc = tID + 8 * k;
            uint32_t a0 = tf32_bits(hs[(r0t)     * HS + kc]);
            uint32_t a1 = tf32_bits(hs[(r0t + 8) * HS + kc]);
            uint32_t a2 = tf32_bits(hs[(r0t)     * HS + kc + 4]);
            uint32_t a3 = tf32_bits(hs[(r0t + 8) * HS + kc + 4]);
            int krow = k * 8 + tID;
#pragma unroll
            for (int n = 0; n < 16; n++) {
                int n0 = nhalf * 128 + n * 8 + gID;
                uint32_t b0 = __float_as_uint(Wb[krow * WS_STRIDE + n0]);
                uint32_t b1 = __float_as_uint(Wb[(krow + 4) * WS_STRIDE + n0]);
                mma_tf32(acc[n], a0, a1, a2, a3, b0, b1);
            }
        }
        __syncthreads();
    }

    // epilogue: fp32 Wh + tf32-rounded Whr
    int cb = nhalf * 128 + tID * 2;
#pragma unroll
    for (int n = 0; n < 16; n++) {
        int cc = cb + n * 8;
        size_t o0 = (size_t)(i0 + r0t) * FOUT + cc;
        size_t o1 = (size_t)(i0 + r0t + 8) * FOUT + cc;
        *(float2*)&d_Wh[o0] = make_float2(acc[n][0], acc[n][1]);
        *(float2*)&d_Wh[o1] = make_float2(acc[n][2], acc[n][3]);
        *(float2*)&d_Whr[o0] =
            make_float2(__uint_as_float(tf32_bits(acc[n][0])),
                        __uint_as_float(tf32_bits(acc[n][1])));
        *(float2*)&d_Whr[o1] =
            make_float2(__uint_as_float(tf32_bits(acc[n][2])),
                        __uint_as_float(tf32_bits(acc[n][3])));
    }
}

// ---------------- f1, f2 and global max(f2) ----------------
__global__ void f12_kernel(const float* __restrict__ a) {
    int lane = threadIdx.x & 31, warp = threadIdx.x >> 5;
    int row  = blockIdx.x * 8 + warp;
    const float* wr = &d_Wh[(size_t)row * FOUT];
    float s1 = 0.f, s2 = 0.f;
#pragma unroll
    for (int q = 0; q < 2; q++) {
        int c = q * 128 + lane * 4;
        float4 v  = *(const float4*)&wr[c];
        float4 a1 = *(const float4*)&a[c];
        float4 a2 = *(const float4*)&a[FOUT + c];
        s1 += v.x * a1.x + v.y * a1.y + v.z * a1.z + v.w * a1.w;
        s2 += v.x * a2.x + v.y * a2.y + v.z * a2.z + v.w * a2.w;
    }
#pragma unroll
    for (int o = 16; o; o >>= 1) {
        s1 += __shfl_xor_sync(0xffffffffu, s1, o);
        s2 += __shfl_xor_sync(0xffffffffu, s2, o);
    }
    if (lane == 0) {
        d_f1[row] = s1;
        d_f2[row] = s2;
        int b   = __float_as_int(s2);
        int key = b >= 0 ? b : (b ^ 0x7fffffff);
        atomicMax(&d_gmaxkey, key);
    }
}

// ---------------- factorized softmax weights ----------------
__global__ void pexp_kernel() {
    int i = blockIdx.x * 256 + threadIdx.x;
    int kk = d_gmaxkey;
    float gm = __int_as_float(kk >= 0 ? kk : (kk ^ 0x7fffffff));
    float f1 = d_f1[i], f2 = d_f2[i];
    float u  = f1 + gm;
    float m  = u > 0.f ? u : LALPHA * u;
    d_A[i] = __expf(u - m);
    d_C[i] = __expf(LALPHA * u - m);
    float v = f2 - gm;
    d_B[i] = __expf(v);
    d_D[i] = __expf(LALPHA * v);
}

// ---------------- staging helpers (cp.async) ----------------
__device__ __forceinline__ void stage_slot(uint32_t sbase, const int* adj,
                                           int s, int t) {
    int buf = s & 1;
    int ib  = s >> 7;
    int jg  = (s & (CPB - 1)) * KC;
    uint32_t wb = sbase + (uint32_t)(buf * WHTILE_WORDS * 4);
#pragma unroll
    for (int u = 0; u < 8; u++) {
        int f = u * 512 + t;
        int row = f >> 6, c4 = (f & 63) << 2;
        cp_async16(wb + (uint32_t)((row * WS_STRIDE + c4) * 4),
                   &d_Whr[(size_t)(jg + row) * FOUT + c4]);
    }
    uint32_t ab = sbase + (uint32_t)((SM_ADJ + buf * ADJTILE_WORDS) * 4);
    const int* abase = adj + (size_t)ib * M_TILE * Nn + jg;
#pragma unroll
    for (int u = 0; u < 4; u++) {
        int f = u * 512 + t;
        int row = f >> 4, seg = (f & 15) << 2;
        cp_async16(ab + (uint32_t)((row * ADJ_STRIDE + seg) * 4),
                   abase + (size_t)row * Nn + seg);
    }
    if (t < 48) {
        uint32_t fb = sbase + (uint32_t)((SM_FBD + buf * 192 + t * 4) * 4);
        const float* src = (t < 16) ? &d_f2[jg + t * 4]
                         : (t < 32) ? &d_B[jg + (t - 16) * 4]
                                    : &d_D[jg + (t - 32) * 4];
        cp_async16(fb, src);
    }
}

// ---------------- fused attention @ Wh via mma.sync tf32 ----------------
__global__ void __launch_bounds__(512, 1) attn_mma(const int* __restrict__ adj) {
    extern __shared__ float sm[];
    uint32_t sbase = smem_u32(sm);

    int t    = threadIdx.x;
    int lane = t & 31, wid = t >> 5;
    int mstrip = wid >> 1, nhalf = wid & 1;
    int gID = lane >> 2, tID = lane & 3;
    int r0t = mstrip * 16 + gID;

    int s0 = (int)(((long long)blockIdx.x * TOTSLOT) / NCTA);
    int s1 = (int)(((long long)(blockIdx.x + 1) * TOTSLOT) / NCTA);

    float acc[16][4];
#pragma unroll
    for (int n = 0; n < 16; n++)
#pragma unroll
        for (int u = 0; u < 4; u++) acc[n][u] = 0.f;
    float ssum0 = 0.f, ssum1 = 0.f;

    float f1a = 0.f, Aa = 0.f, Ca = 0.f;
    float f1b = 0.f, Ab = 0.f, Cb = 0.f;
    int cur_ib = -1;

    stage_slot(sbase, adj, s0, t);
    cp_commit();

    for (int s = s0; s < s1; s++) {
        int ib = s >> 7;
        int buf = s & 1;

        if (ib != cur_ib) {
            if (cur_ib >= 0) {
                float sa = ssum0 + __shfl_xor_sync(0xffffffffu, ssum0, 1);
                sa += __shfl_xor_sync(0xffffffffu, sa, 2);
                float sb = ssum1 + __shfl_xor_sync(0xffffffffu, ssum1, 1);
                sb += __shfl_xor_sync(0xffffffffu, sb, 2);
                int base = cur_ib * M_TILE;
                if (tID == 0 && nhalf == 0) {
                    atomicAdd(&d_ssum[base + r0t], sa);
                    atomicAdd(&d_ssum[base + r0t + 8], sb);
                }
                float* np = &d_num[(size_t)(base) * FOUT];
                int cb = nhalf * 128 + tID * 2;
#pragma unroll
                for (int n = 0; n < 16; n++) {
                    int cc = cb + n * 8;
                    atomicAdd(&np[(size_t)r0t * FOUT + cc],       acc[n][0]);
                    atomicAdd(&np[(size_t)r0t * FOUT + cc + 1],   acc[n][1]);
                    atomicAdd(&np[(size_t)(r0t + 8) * FOUT + cc],     acc[n][2]);
                    atomicAdd(&np[(size_t)(r0t + 8) * FOUT + cc + 1], acc[n][3]);
                }
#pragma unroll
                for (int n = 0; n < 16; n++)
#pragma unroll
                    for (int u = 0; u < 4; u++) acc[n][u] = 0.f;
                ssum0 = 0.f; ssum1 = 0.f;
            }
            int base = ib * M_TILE;
            f1a = d_f1[base + r0t];     f1b = d_f1[base + r0t + 8];
            Aa  = d_A[base + r0t];      Ab  = d_A[base + r0t + 8];
            Ca  = d_C[base + r0t];      Cb  = d_C[base + r0t + 8];
            cur_ib = ib;
        }

        cp_wait<0>();
        __syncthreads();

        if (s + 1 < s1) {
            stage_slot(sbase, adj, s + 1, t);
            cp_commit();
        }

        const float* Wb   = sm + buf * WHTILE_WORDS;
        const int*   adjS = (const int*)(sm + SM_ADJ + buf * ADJTILE_WORDS);
        const float* fbd  = sm + SM_FBD + buf * 192;

#pragma unroll
        for (int k = 0; k < 8; k++) {
            int j0 = tID + 8 * k, j1 = j0 + 4;
            int ad00 = adjS[r0t * ADJ_STRIDE + j0];
            int ad10 = adjS[(r0t + 8) * ADJ_STRIDE + j0];
            int ad01 = adjS[r0t * ADJ_STRIDE + j1];
            int ad11 = adjS[(r0t + 8) * ADJ_STRIDE + j1];
            float f20 = fbd[j0], B0 = fbd[64 + j0], D0 = fbd[128 + j0];
            float f21 = fbd[j1], B1 = fbd[64 + j1], D1 = fbd[128 + j1];
            float e00 = f1a + f20, e10 = f1b + f20;
            float e01 = f1a + f21, e11 = f1b + f21;
            float p00 = (ad00 > 0) ? (e00 > 0.f ? Aa * B0 : Ca * D0) : 0.f;
            float p10 = (ad10 > 0) ? (e10 > 0.f ? Ab * B0 : Cb * D0) : 0.f;
            float p01 = (ad01 > 0) ? (e01 > 0.f ? Aa * B1 : Ca * D1) : 0.f;
            float p11 = (ad11 > 0) ? (e11 > 0.f ? Ab * B1 : Cb * D1) : 0.f;
            if (nhalf == 0) { ssum0 += p00 + p01; ssum1 += p10 + p11; }
            uint32_t a0 = tf32_bits(p00), a1 = tf32_bits(p10);
            uint32_t a2 = tf32_bits(p01), a3 = tf32_bits(p11);
            int krow = k * 8 + tID;
#pragma unroll
            for (int n = 0; n < 16; n++) {
                int n0 = nhalf * 128 + n * 8 + gID;
                uint32_t b0 = __float_as_uint(Wb[krow * WS_STRIDE + n0]);
                uint32_t b1 = __float_as_uint(Wb[(krow + 4) * WS_STRIDE + n0]);
                mma_tf32(acc[n], a0, a1, a2, a3, b0, b1);
            }
        }
    }

    {
        float sa = ssum0 + __shfl_xor_sync(0xffffffffu, ssum0, 1);
        sa += __shfl_xor_sync(0xffffffffu, sa, 2);
        float sb = ssum1 + __shfl_xor_sync(0xffffffffu, ssum1, 1);
        sb += __shfl_xor_sync(0xffffffffu, sb, 2);
        int base = cur_ib * M_TILE;
        if (tID == 0 && nhalf == 0) {
            atomicAdd(&d_ssum[base + r0t], sa);
            atomicAdd(&d_ssum[base + r0t + 8], sb);
        }
        float* np = &d_num[(size_t)(base) * FOUT];
        int cb = nhalf * 128 + tID * 2;
#pragma unroll
        for (int n = 0; n < 16; n++) {
            int cc = cb + n * 8;
            atomicAdd(&np[(size_t)r0t * FOUT + cc],       acc[n][0]);
            atomicAdd(&np[(size_t)r0t * FOUT + cc + 1],   acc[n][1]);
            atomicAdd(&np[(size_t)(r0t + 8) * FOUT + cc],     acc[n][2]);
            atomicAdd(&np[(size_t)(r0t + 8) * FOUT + cc + 1], acc[n][3]);
        }
    }
}

// ---------------- normalize + ELU ----------------
__global__ void elu_kernel(float* __restrict__ out) {
    int i = blockIdx.x, c = threadIdx.x;
    float x = d_num[(size_t)i * FOUT + c] / d_ssum[i];
    out[(size_t)i * FOUT + c] = x > 0.f ? x : expm1f(x);
}

extern "C" void kernel_launch(void* const* d_in, const int* in_sizes, int n_in,
                              void* d_out, int out_size) {
    const float* h   = (const float*)d_in[0];
    const int*   adj = (const int*)d_in[1];
    const float* W   = (const float*)d_in[2];
    const float* a   = (const float*)d_in[3];
    float* out = (float*)d_out;

    cudaFuncSetAttribute(attn_mma, cudaFuncAttributeMaxDynamicSharedMemorySize, SMEM_DYN);
    cudaFuncSetAttribute(gemm_wh_mma, cudaFuncAttributeMaxDynamicSharedMemorySize, GSMEM_DYN);

    zero_kernel<<<(Nn * FOUT) / 1024, 256>>>();
    wround_kernel<<<(FIN * FOUT) / 1024, 256>>>(W);
    gemm_wh_mma<<<Nn / GM, 256, GSMEM_DYN>>>(h);
    f12_kernel<<<Nn / 8, 256>>>(a);
    pexp_kernel<<<Nn / 256, 256>>>();
    attn_mma<<<NCTA, 512, SMEM_DYN>>>(adj);
    elu_kernel<<<Nn, 256>>>(out);
}

// round 10
// speedup vs baseline: 1.9171x; 1.0262x over previous
#include <cuda_runtime.h>
#include <cuda_bf16.h>
#include <cstdint>

#define Nn     8192
#define FIN    512
#define FOUT   256
#define LALPHA 0.2f
#define M_TILE 128
#define KC     64
#define NBLK   (Nn / M_TILE)          // 64 row blocks
#define CPB    (Nn / KC)              // 128 chunks per row block
#define TOTSLOT (NBLK * CPB)          // 8192
#define NCTA   148

#define WS_STRIDE 264                 // Wh/W tile row stride (words)
#define ADJ_STRIDE 68                 // adj tile row stride (words)
#define WHTILE_WORDS (KC * WS_STRIDE)         // 16896
#define ADJTILE_WORDS (M_TILE * ADJ_STRIDE)   // 8704
#define SM_ADJ (2 * WHTILE_WORDS)             // 33792
#define SM_FBD (SM_ADJ + 2 * ADJTILE_WORDS)   // 51200
#define SMEM_DYN ((SM_FBD + 2 * 192) * 4)     // 206336 B

// gemm_wh_mma tiles
#define GM      64
#define HS      68
#define HS_WORDS (GM * HS)                    // 4352
#define GSM_A   (2 * HS_WORDS + 2 * WHTILE_WORDS)          // a1/a2 staging
#define GSMEM_DYN ((GSM_A + 512) * 4)                      // 172032 B

// ---------------- scratch (device globals: allowed) ----------------
__device__ float d_Whr[(size_t)Nn * FOUT];           // 8 MB tf32-rounded
__device__ float d_Wr[(size_t)FIN * FOUT];           // 512 KB tf32-rounded W
__device__ float d_f1[Nn];
__device__ float d_f2[Nn];
__device__ float d_A[Nn];
__device__ float d_C[Nn];
__device__ float d_B[Nn];
__device__ float d_D[Nn];
__device__ int   d_gmaxkey;
__device__ float d_num[(size_t)Nn * FOUT];           // 8 MB (atomic accum)
__device__ float d_ssum[Nn];

__device__ __forceinline__ uint32_t tf32_bits(float x) {
    uint32_t r; asm("cvt.rna.tf32.f32 %0, %1;" : "=r"(r) : "f"(x)); return r;
}
__device__ __forceinline__ void mma_tf32(float* d, uint32_t a0, uint32_t a1,
                                         uint32_t a2, uint32_t a3,
                                         uint32_t b0, uint32_t b1) {
    asm volatile(
        "mma.sync.aligned.m16n8k8.row.col.f32.tf32.tf32.f32 "
        "{%0,%1,%2,%3}, {%4,%5,%6,%7}, {%8,%9}, {%0,%1,%2,%3};"
        : "+f"(d[0]), "+f"(d[1]), "+f"(d[2]), "+f"(d[3])
        : "r"(a0), "r"(a1), "r"(a2), "r"(a3), "r"(b0), "r"(b1));
}
__device__ __forceinline__ uint32_t smem_u32(const void* p) {
    uint32_t a;
    asm("{ .reg .u64 t; cvta.to.shared.u64 t, %1; cvt.u32.u64 %0, t; }"
        : "=r"(a) : "l"(p));
    return a;
}
__device__ __forceinline__ void cp_async16(uint32_t sa, const void* g) {
    asm volatile("cp.async.ca.shared.global [%0], [%1], 16;" :: "r"(sa), "l"(g) : "memory");
}
__device__ __forceinline__ void cp_commit() {
    asm volatile("cp.async.commit_group;" ::: "memory");
}
template <int N> __device__ __forceinline__ void cp_wait() {
    asm volatile("cp.async.wait_group %0;" :: "n"(N) : "memory");
}

// ---------------- zero / init ----------------
__global__ void zero_kernel() {
    if (blockIdx.x == 0 && threadIdx.x == 0) d_gmaxkey = (int)0x80000000;
    size_t i = ((size_t)blockIdx.x * 256 + threadIdx.x) * 4;
    if (i < (size_t)Nn * FOUT)
        *(float4*)&d_num[i] = make_float4(0.f, 0.f, 0.f, 0.f);
    if (i < Nn) {
        *(float4*)&d_ssum[i] = make_float4(0.f, 0.f, 0.f, 0.f);
        *(float4*)&d_f1[i]   = make_float4(0.f, 0.f, 0.f, 0.f);
        *(float4*)&d_f2[i]   = make_float4(0.f, 0.f, 0.f, 0.f);
    }
}

// ---------------- round W to tf32 ----------------
__global__ void wround_kernel(const float* __restrict__ W) {
    int i = (blockIdx.x * 256 + threadIdx.x) * 4;
    float4 v = *(const float4*)&W[i];
    float4 o;
    o.x = __uint_as_float(tf32_bits(v.x));
    o.y = __uint_as_float(tf32_bits(v.y));
    o.z = __uint_as_float(tf32_bits(v.z));
    o.w = __uint_as_float(tf32_bits(v.w));
    *(float4*)&d_Wr[i] = o;
}

// ---------------- Wh = h @ W via mma.sync tf32 (+ fused f1/f2) ----------------
__device__ __forceinline__ void stage_g(uint32_t sbase, const float* __restrict__ h,
                                        int i0, int c, int t) {
    int buf = c & 1;
    int k0  = c * KC;
    uint32_t hb = sbase + (uint32_t)(buf * HS_WORDS * 4);
#pragma unroll
    for (int u = 0; u < 4; u++) {
        int f = u * 256 + t;
        int row = f >> 4, seg = (f & 15) << 2;
        cp_async16(hb + (uint32_t)((row * HS + seg) * 4),
                   &h[(size_t)(i0 + row) * FIN + k0 + seg]);
    }
    uint32_t wb = sbase + (uint32_t)((2 * HS_WORDS + buf * WHTILE_WORDS) * 4);
#pragma unroll
    for (int u = 0; u < 16; u++) {
        int f = u * 256 + t;
        int row = f >> 6, c4 = (f & 63) << 2;
        cp_async16(wb + (uint32_t)((row * WS_STRIDE + c4) * 4),
                   &d_Wr[(size_t)(k0 + row) * FOUT + c4]);
    }
}

__global__ void __launch_bounds__(256, 1) gemm_wh_mma(const float* __restrict__ h,
                                                      const float* __restrict__ a) {
    extern __shared__ float gsm[];
    uint32_t sbase = smem_u32(gsm);
    float* as = gsm + GSM_A;   // a1[256] then a2[256]

    int t    = threadIdx.x;
    int lane = t & 31, wid = t >> 5;
    int mstrip = wid >> 1, nhalf = wid & 1;
    int gID = lane >> 2, tID = lane & 3;
    int r0t = mstrip * 16 + gID;
    int i0  = blockIdx.x * GM;

    if (t < 128) *(float4*)&as[t * 4] = *(const float4*)&a[t * 4];

    float acc[16][4];
#pragma unroll
    for (int n = 0; n < 16; n++)
#pragma unroll
        for (int u = 0; u < 4; u++) acc[n][u] = 0.f;

    stage_g(sbase, h, i0, 0, t);
    cp_commit();

    for (int c = 0; c < FIN / KC; c++) {
        int buf = c & 1;
        cp_wait<0>();
        __syncthreads();
        if (c + 1 < FIN / KC) {
            stage_g(sbase, h, i0, c + 1, t);
            cp_commit();
        }
        const float* hs = gsm + buf * HS_WORDS;
        const float* Wb = gsm + 2 * HS_WORDS + buf * WHTILE_WORDS;
#pragma unroll
        for (int k = 0; k < 8; k++) {
            int kc = tID + 8 * k;
            uint32_t a0 = tf32_bits(hs[(r0t)     * HS + kc]);
            uint32_t a1 = tf32_bits(hs[(r0t + 8) * HS + kc]);
            uint32_t a2 = tf32_bits(hs[(r0t)     * HS + kc + 4]);
            uint32_t a3 = tf32_bits(hs[(r0t + 8) * HS + kc + 4]);
            int krow = k * 8 + tID;
#pragma unroll
            for (int n = 0; n < 16; n++) {
                int n0 = nhalf * 128 + n * 8 + gID;
                uint32_t b0 = __float_as_uint(Wb[krow * WS_STRIDE + n0]);
                uint32_t b1 = __float_as_uint(Wb[(krow + 4) * WS_STRIDE + n0]);
                mma_tf32(acc[n], a0, a1, a2, a3, b0, b1);
            }
        }
        __syncthreads();
    }

    // epilogue: tf32-rounded Whr + fused f1/f2 partial dots
    float s1a = 0.f, s2a = 0.f, s1b = 0.f, s2b = 0.f;
    int cb = nhalf * 128 + tID * 2;
#pragma unroll
    for (int n = 0; n < 16; n++) {
        int cc = cb + n * 8;
        size_t o0 = (size_t)(i0 + r0t) * FOUT + cc;
        size_t o1 = (size_t)(i0 + r0t + 8) * FOUT + cc;
        *(float2*)&d_Whr[o0] =
            make_float2(__uint_as_float(tf32_bits(acc[n][0])),
                        __uint_as_float(tf32_bits(acc[n][1])));
        *(float2*)&d_Whr[o1] =
            make_float2(__uint_as_float(tf32_bits(acc[n][2])),
                        __uint_as_float(tf32_bits(acc[n][3])));
        float a10 = as[cc], a11 = as[cc + 1];
        float a20 = as[256 + cc], a21 = as[256 + cc + 1];
        s1a += acc[n][0] * a10 + acc[n][1] * a11;
        s2a += acc[n][0] * a20 + acc[n][1] * a21;
        s1b += acc[n][2] * a10 + acc[n][3] * a11;
        s2b += acc[n][2] * a20 + acc[n][3] * a21;
    }
#pragma unroll
    for (int o = 1; o <= 2; o <<= 1) {
        s1a += __shfl_xor_sync(0xffffffffu, s1a, o);
        s2a += __shfl_xor_sync(0xffffffffu, s2a, o);
        s1b += __shfl_xor_sync(0xffffffffu, s1b, o);
        s2b += __shfl_xor_sync(0xffffffffu, s2b, o);
    }
    if (tID == 0) {
        atomicAdd(&d_f1[i0 + r0t], s1a);
        atomicAdd(&d_f2[i0 + r0t], s2a);
        atomicAdd(&d_f1[i0 + r0t + 8], s1b);
        atomicAdd(&d_f2[i0 + r0t + 8], s2b);
    }
}

// ---------------- global max(f2) ----------------
__global__ void maxf2_kernel() {
    int i = blockIdx.x * 256 + threadIdx.x;
    float v = d_f2[i];
#pragma unroll
    for (int o = 16; o; o >>= 1)
        v = fmaxf(v, __shfl_xor_sync(0xffffffffu, v, o));
    if ((threadIdx.x & 31) == 0) {
        int b = __float_as_int(v);
        int key = b >= 0 ? b : (b ^ 0x7fffffff);
        atomicMax(&d_gmaxkey, key);
    }
}

// ---------------- factorized softmax weights ----------------
__global__ void pexp_kernel() {
    int i = blockIdx.x * 256 + threadIdx.x;
    int kk = d_gmaxkey;
    float gm = __int_as_float(kk >= 0 ? kk : (kk ^ 0x7fffffff));
    float f1 = d_f1[i], f2 = d_f2[i];
    float u  = f1 + gm;
    float m  = u > 0.f ? u : LALPHA * u;
    d_A[i] = __expf(u - m);
    d_C[i] = __expf(LALPHA * u - m);
    float v = f2 - gm;
    d_B[i] = __expf(v);
    d_D[i] = __expf(LALPHA * v);
}

// ---------------- staging helpers (cp.async) ----------------
__device__ __forceinline__ void stage_slot(uint32_t sbase, const int* adj,
                                           int s, int t) {
    int buf = s & 1;
    int ib  = s >> 7;
    int jg  = (s & (CPB - 1)) * KC;
    uint32_t wb = sbase + (uint32_t)(buf * WHTILE_WORDS * 4);
#pragma unroll
    for (int u = 0; u < 8; u++) {
        int f = u * 512 + t;
        int row = f >> 6, c4 = (f & 63) << 2;
        cp_async16(wb + (uint32_t)((row * WS_STRIDE + c4) * 4),
                   &d_Whr[(size_t)(jg + row) * FOUT + c4]);
    }
    uint32_t ab = sbase + (uint32_t)((SM_ADJ + buf * ADJTILE_WORDS) * 4);
    const int* abase = adj + (size_t)ib * M_TILE * Nn + jg;
#pragma unroll
    for (int u = 0; u < 4; u++) {
        int f = u * 512 + t;
        int row = f >> 4, seg = (f & 15) << 2;
        cp_async16(ab + (uint32_t)((row * ADJ_STRIDE + seg) * 4),
                   abase + (size_t)row * Nn + seg);
    }
    if (t < 48) {
        uint32_t fb = sbase + (uint32_t)((SM_FBD + buf * 192 + t * 4) * 4);
        const float* src = (t < 16) ? &d_f2[jg + t * 4]
                         : (t < 32) ? &d_B[jg + (t - 16) * 4]
                                    : &d_D[jg + (t - 32) * 4];
        cp_async16(fb, src);
    }
}

// ---------------- fused attention @ Wh via mma.sync tf32 ----------------
__global__ void __launch_bounds__(512, 1) attn_mma(const int* __restrict__ adj) {
    extern __shared__ float sm[];
    uint32_t sbase = smem_u32(sm);

    int t    = threadIdx.x;
    int lane = t & 31, wid = t >> 5;
    int mstrip = wid >> 1, nhalf = wid & 1;
    int gID = lane >> 2, tID = lane & 3;
    int r0t = mstrip * 16 + gID;

    int s0 = (int)(((long long)blockIdx.x * TOTSLOT) / NCTA);
    int s1 = (int)(((long long)(blockIdx.x + 1) * TOTSLOT) / NCTA);

    float acc[16][4];
#pragma unroll
    for (int n = 0; n < 16; n++)
#pragma unroll
        for (int u = 0; u < 4; u++) acc[n][u] = 0.f;
    float ssum0 = 0.f, ssum1 = 0.f;

    float f1a = 0.f, Aa = 0.f, Ca = 0.f;
    float f1b = 0.f, Ab = 0.f, Cb = 0.f;
    int cur_ib = -1;

    stage_slot(sbase, adj, s0, t);
    cp_commit();

    for (int s = s0; s < s1; s++) {
        int ib = s >> 7;
        int buf = s & 1;

        if (ib != cur_ib) {
            if (cur_ib >= 0) {
                float sa = ssum0 + __shfl_xor_sync(0xffffffffu, ssum0, 1);
                sa += __shfl_xor_sync(0xffffffffu, sa, 2);
                float sb = ssum1 + __shfl_xor_sync(0xffffffffu, ssum1, 1);
                sb += __shfl_xor_sync(0xffffffffu, sb, 2);
                int base = cur_ib * M_TILE;
                if (tID == 0 && nhalf == 0) {
                    atomicAdd(&d_ssum[base + r0t], sa);
                    atomicAdd(&d_ssum[base + r0t + 8], sb);
                }
                float* np = &d_num[(size_t)(base) * FOUT];
                int cb = nhalf * 128 + tID * 2;
#pragma unroll
                for (int n = 0; n < 16; n++) {
                    int cc = cb + n * 8;
                    atomicAdd(&np[(size_t)r0t * FOUT + cc],       acc[n][0]);
                    atomicAdd(&np[(size_t)r0t * FOUT + cc + 1],   acc[n][1]);
                    atomicAdd(&np[(size_t)(r0t + 8) * FOUT + cc],     acc[n][2]);
                    atomicAdd(&np[(size_t)(r0t + 8) * FOUT + cc + 1], acc[n][3]);
                }
#pragma unroll
                for (int n = 0; n < 16; n++)
#pragma unroll
                    for (int u = 0; u < 4; u++) acc[n][u] = 0.f;
                ssum0 = 0.f; ssum1 = 0.f;
            }
            int base = ib * M_TILE;
            f1a = d_f1[base + r0t];     f1b = d_f1[base + r0t + 8];
            Aa  = d_A[base + r0t];      Ab  = d_A[base + r0t + 8];
            Ca  = d_C[base + r0t];      Cb  = d_C[base + r0t + 8];
            cur_ib = ib;
        }

        cp_wait<0>();
        __syncthreads();

        if (s + 1 < s1) {
            stage_slot(sbase, adj, s + 1, t);
            cp_commit();
        }

        const float* Wb   = sm + buf * WHTILE_WORDS;
        const int*   adjS = (const int*)(sm + SM_ADJ + buf * ADJTILE_WORDS);
        const float* fbd  = sm + SM_FBD + buf * 192;

#pragma unroll
        for (int k = 0; k < 8; k++) {
            int j0 = tID + 8 * k, j1 = j0 + 4;
            int ad00 = adjS[r0t * ADJ_STRIDE + j0];
            int ad10 = adjS[(r0t + 8) * ADJ_STRIDE + j0];
            int ad01 = adjS[r0t * ADJ_STRIDE + j1];
            int ad11 = adjS[(r0t + 8) * ADJ_STRIDE + j1];
            float f20 = fbd[j0], B0 = fbd[64 + j0], D0 = fbd[128 + j0];
            float f21 = fbd[j1], B1 = fbd[64 + j1], D1 = fbd[128 + j1];
            float e00 = f1a + f20, e10 = f1b + f20;
            float e01 = f1a + f21, e11 = f1b + f21;
            float p00 = (ad00 > 0) ? (e00 > 0.f ? Aa * B0 : Ca * D0) : 0.f;
            float p10 = (ad10 > 0) ? (e10 > 0.f ? Ab * B0 : Cb * D0) : 0.f;
            float p01 = (ad01 > 0) ? (e01 > 0.f ? Aa * B1 : Ca * D1) : 0.f;
            float p11 = (ad11 > 0) ? (e11 > 0.f ? Ab * B1 : Cb * D1) : 0.f;
            if (nhalf == 0) { ssum0 += p00 + p01; ssum1 += p10 + p11; }
            uint32_t a0 = tf32_bits(p00), a1 = tf32_bits(p10);
            uint32_t a2 = tf32_bits(p01), a3 = tf32_bits(p11);
            int krow = k * 8 + tID;
#pragma unroll
            for (int n = 0; n < 16; n++) {
                int n0 = nhalf * 128 + n * 8 + gID;
                uint32_t b0 = __float_as_uint(Wb[krow * WS_STRIDE + n0]);
                uint32_t b1 = __float_as_uint(Wb[(krow + 4) * WS_STRIDE + n0]);
                mma_tf32(acc[n], a0, a1, a2, a3, b0, b1);
            }
        }
    }

    {
        float sa = ssum0 + __shfl_xor_sync(0xffffffffu, ssum0, 1);
        sa += __shfl_xor_sync(0xffffffffu, sa, 2);
        float sb = ssum1 + __shfl_xor_sync(0xffffffffu, ssum1, 1);
        sb += __shfl_xor_sync(0xffffffffu, sb, 2);
        int base = cur_ib * M_TILE;
        if (tID == 0 && nhalf == 0) {
            atomicAdd(&d_ssum[base + r0t], sa);
            atomicAdd(&d_ssum[base + r0t + 8], sb);
        }
        float* np = &d_num[(size_t)(base) * FOUT];
        int cb = nhalf * 128 + tID * 2;
#pragma unroll
        for (int n = 0; n < 16; n++) {
            int cc = cb + n * 8;
            atomicAdd(&np[(size_t)r0t * FOUT + cc],       acc[n][0]);
            atomicAdd(&np[(size_t)r0t * FOUT + cc + 1],   acc[n][1]);
            atomicAdd(&np[(size_t)(r0t + 8) * FOUT + cc],     acc[n][2]);
            atomicAdd(&np[(size_t)(r0t + 8) * FOUT + cc + 1], acc[n][3]);
        }
    }
}

// ---------------- normalize + ELU (vectorized) ----------------
__global__ void elu_kernel(float* __restrict__ out) {
    int idx = blockIdx.x * 256 + threadIdx.x;     // one float4 per thread
    int row = idx >> 6;                           // 64 float4 per row
    float s = d_ssum[row];
    float4 v = *(const float4*)&d_num[(size_t)idx * 4];
    float4 o;
    float x;
    x = v.x / s; o.x = x > 0.f ? x : expm1f(x);
    x = v.y / s; o.y = x > 0.f ? x : expm1f(x);
    x = v.z / s; o.z = x > 0.f ? x : expm1f(x);
    x = v.w / s; o.w = x > 0.f ? x : expm1f(x);
    *(float4*)&out[(size_t)idx * 4] = o;
}

extern "C" void kernel_launch(void* const* d_in, const int* in_sizes, int n_in,
                              void* d_out, int out_size) {
    const float* h   = (const float*)d_in[0];
    const int*   adj = (const int*)d_in[1];
    const float* W   = (const float*)d_in[2];
    const float* a   = (const float*)d_in[3];
    float* out = (float*)d_out;

    cudaFuncSetAttribute(attn_mma, cudaFuncAttributeMaxDynamicSharedMemorySize, SMEM_DYN);
    cudaFuncSetAttribute(gemm_wh_mma, cudaFuncAttributeMaxDynamicSharedMemorySize, GSMEM_DYN);

    zero_kernel<<<(Nn * FOUT) / 1024, 256>>>();
    wround_kernel<<<(FIN * FOUT) / 1024, 256>>>(W);
    gemm_wh_mma<<<Nn / GM, 256, GSMEM_DYN>>>(h, a);
    maxf2_kernel<<<Nn / 256, 256>>>();
    pexp_kernel<<<Nn / 256, 256>>>();
    attn_mma<<<NCTA, 512, SMEM_DYN>>>(adj);
    elu_kernel<<<(Nn * FOUT) / 1024, 256>>>(out);
}

// round 11
// speedup vs baseline: 1.9304x; 1.0069x over previous
#include <cuda_runtime.h>
#include <cuda_bf16.h>
#include <cstdint>

#define Nn     8192
#define FIN    512
#define FOUT   256
#define LALPHA 0.2f
#define M_TILE 128
#define KC     64
#define NBLK   (Nn / M_TILE)          // 64 row blocks
#define CPB    (Nn / KC)              // 128 chunks per row block
#define TOTSLOT (NBLK * CPB)          // 8192
#define NCTA   148

#define WS_STRIDE 264                 // Wh/W tile row stride (words)
#define ADJ_STRIDE 68                 // adj tile row stride (words)
#define WHTILE_WORDS (KC * WS_STRIDE)         // 16896
#define ADJTILE_WORDS (M_TILE * ADJ_STRIDE)   // 8704
#define SM_ADJ (2 * WHTILE_WORDS)             // 33792
#define SM_FBD (SM_ADJ + 2 * ADJTILE_WORDS)   // 51200
#define SMEM_DYN ((SM_FBD + 2 * 192) * 4)     // 206336 B

// gemm_wh_mma tiles
#define GM      64
#define HS      68
#define HS_WORDS (GM * HS)                    // 4352
#define GSM_A   (2 * HS_WORDS + 2 * WHTILE_WORDS)          // a1/a2 staging
#define GSMEM_DYN ((GSM_A + 512) * 4)                      // 172032 B

// ---------------- scratch (device globals: allowed) ----------------
__device__ float d_Whr[(size_t)Nn * FOUT];           // 8 MB tf32-rounded
__device__ float d_Wr[(size_t)FIN * FOUT];           // 512 KB tf32-rounded W
__device__ float d_f1[Nn];
__device__ float d_f2[Nn];
__device__ float d_A[Nn];
__device__ float d_C[Nn];
__device__ float d_B[Nn];
__device__ float d_D[Nn];
__device__ int   d_gmaxkey;
__device__ float d_num[(size_t)Nn * FOUT];           // 8 MB (atomic accum)
__device__ float d_ssum[Nn];

__device__ __forceinline__ uint32_t tf32_bits(float x) {
    uint32_t r; asm("cvt.rna.tf32.f32 %0, %1;" : "=r"(r) : "f"(x)); return r;
}
__device__ __forceinline__ void mma_tf32(float* d, uint32_t a0, uint32_t a1,
                                         uint32_t a2, uint32_t a3,
                                         uint32_t b0, uint32_t b1) {
    asm volatile(
        "mma.sync.aligned.m16n8k8.row.col.f32.tf32.tf32.f32 "
        "{%0,%1,%2,%3}, {%4,%5,%6,%7}, {%8,%9}, {%0,%1,%2,%3};"
        : "+f"(d[0]), "+f"(d[1]), "+f"(d[2]), "+f"(d[3])
        : "r"(a0), "r"(a1), "r"(a2), "r"(a3), "r"(b0), "r"(b1));
}
__device__ __forceinline__ uint32_t smem_u32(const void* p) {
    uint32_t a;
    asm("{ .reg .u64 t; cvta.to.shared.u64 t, %1; cvt.u32.u64 %0, t; }"
        : "=r"(a) : "l"(p));
    return a;
}
__device__ __forceinline__ void cp_async16(uint32_t sa, const void* g) {
    asm volatile("cp.async.ca.shared.global [%0], [%1], 16;" :: "r"(sa), "l"(g) : "memory");
}
__device__ __forceinline__ void cp_commit() {
    asm volatile("cp.async.commit_group;" ::: "memory");
}
template <int N> __device__ __forceinline__ void cp_wait() {
    asm volatile("cp.async.wait_group %0;" :: "n"(N) : "memory");
}

// ---------------- init: zero accumulators + round W ----------------
__global__ void init_kernel(const float* __restrict__ W) {
    if (blockIdx.x == 0 && threadIdx.x == 0) d_gmaxkey = (int)0x80000000;
    size_t i = ((size_t)blockIdx.x * 256 + threadIdx.x) * 4;
    *(float4*)&d_num[i] = make_float4(0.f, 0.f, 0.f, 0.f);
    if (i < Nn)
        *(float4*)&d_ssum[i] = make_float4(0.f, 0.f, 0.f, 0.f);
    if (i < (size_t)FIN * FOUT) {
        float4 v = *(const float4*)&W[i];
        float4 o;
        o.x = __uint_as_float(tf32_bits(v.x));
        o.y = __uint_as_float(tf32_bits(v.y));
        o.z = __uint_as_float(tf32_bits(v.z));
        o.w = __uint_as_float(tf32_bits(v.w));
        *(float4*)&d_Wr[i] = o;
    }
}

// ---------------- Wh = h @ W via mma.sync tf32 (+ fused f1/f2/max) ----------------
__device__ __forceinline__ void stage_g(uint32_t sbase, const float* __restrict__ h,
                                        int i0, int c, int t) {
    int buf = c & 1;
    int k0  = c * KC;
    uint32_t hb = sbase + (uint32_t)(buf * HS_WORDS * 4);
#pragma unroll
    for (int u = 0; u < 4; u++) {
        int f = u * 256 + t;
        int row = f >> 4, seg = (f & 15) << 2;
        cp_async16(hb + (uint32_t)((row * HS + seg) * 4),
                   &h[(size_t)(i0 + row) * FIN + k0 + seg]);
    }
    uint32_t wb = sbase + (uint32_t)((2 * HS_WORDS + buf * WHTILE_WORDS) * 4);
#pragma unroll
    for (int u = 0; u < 16; u++) {
        int f = u * 256 + t;
        int row = f >> 6, c4 = (f & 63) << 2;
        cp_async16(wb + (uint32_t)((row * WS_STRIDE + c4) * 4),
                   &d_Wr[(size_t)(k0 + row) * FOUT + c4]);
    }
}

__global__ void __launch_bounds__(256, 1) gemm_wh_mma(const float* __restrict__ h,
                                                      const float* __restrict__ a) {
    extern __shared__ float gsm[];
    uint32_t sbase = smem_u32(gsm);
    float* as = gsm + GSM_A;   // a1[256] then a2[256]

    int t    = threadIdx.x;
    int lane = t & 31, wid = t >> 5;
    int mstrip = wid >> 1, nhalf = wid & 1;
    int gID = lane >> 2, tID = lane & 3;
    int r0t = mstrip * 16 + gID;
    int i0  = blockIdx.x * GM;

    if (t < 128) *(float4*)&as[t * 4] = *(const float4*)&a[t * 4];

    float acc[16][4];
#pragma unroll
    for (int n = 0; n < 16; n++)
#pragma unroll
        for (int u = 0; u < 4; u++) acc[n][u] = 0.f;

    stage_g(sbase, h, i0, 0, t);
    cp_commit();

    for (int c = 0; c < FIN / KC; c++) {
        int buf = c & 1;
        cp_wait<0>();
        __syncthreads();
        if (c + 1 < FIN / KC) {
            stage_g(sbase, h, i0, c + 1, t);
            cp_commit();
        }
        const float* hs = gsm + buf * HS_WORDS;
        const float* Wb = gsm + 2 * HS_WORDS + buf * WHTILE_WORDS;
#pragma unroll
        for (int k = 0; k < 8; k++) {
            int kc = tID + 8 * k;
            uint32_t a0 = tf32_bits(hs[(r0t)     * HS + kc]);
            uint32_t a1 = tf32_bits(hs[(r0t + 8) * HS + kc]);
            uint32_t a2 = tf32_bits(hs[(r0t)     * HS + kc + 4]);
            uint32_t a3 = tf32_bits(hs[(r0t + 8) * HS + kc + 4]);
            int krow = k * 8 + tID;
#pragma unroll
            for (int n = 0; n < 16; n++) {
                int n0 = nhalf * 128 + n * 8 + gID;
                uint32_t b0 = __float_as_uint(Wb[krow * WS_STRIDE + n0]);
                uint32_t b1 = __float_as_uint(Wb[(krow + 4) * WS_STRIDE + n0]);
                mma_tf32(acc[n], a0, a1, a2, a3, b0, b1);
            }
        }
        __syncthreads();
    }

    // epilogue: tf32-rounded Whr + fused f1/f2 + block max(f2)
    float s1a = 0.f, s2a = 0.f, s1b = 0.f, s2b = 0.f;
    int cb = nhalf * 128 + tID * 2;
#pragma unroll
    for (int n = 0; n < 16; n++) {
        int cc = cb + n * 8;
        size_t o0 = (size_t)(i0 + r0t) * FOUT + cc;
        size_t o1 = (size_t)(i0 + r0t + 8) * FOUT + cc;
        *(float2*)&d_Whr[o0] =
            make_float2(__uint_as_float(tf32_bits(acc[n][0])),
                        __uint_as_float(tf32_bits(acc[n][1])));
        *(float2*)&d_Whr[o1] =
            make_float2(__uint_as_float(tf32_bits(acc[n][2])),
                        __uint_as_float(tf32_bits(acc[n][3])));
        float a10 = as[cc], a11 = as[cc + 1];
        float a20 = as[256 + cc], a21 = as[256 + cc + 1];
        s1a += acc[n][0] * a10 + acc[n][1] * a11;
        s2a += acc[n][0] * a20 + acc[n][1] * a21;
        s1b += acc[n][2] * a10 + acc[n][3] * a11;
        s2b += acc[n][2] * a20 + acc[n][3] * a21;
    }
#pragma unroll
    for (int o = 1; o <= 2; o <<= 1) {
        s1a += __shfl_xor_sync(0xffffffffu, s1a, o);
        s2a += __shfl_xor_sync(0xffffffffu, s2a, o);
        s1b += __shfl_xor_sync(0xffffffffu, s1b, o);
        s2b += __shfl_xor_sync(0xffffffffu, s2b, o);
    }
    // cross-nhalf combine via smem (staging area reusable post-sync)
    if (nhalf == 1 && tID == 0) {
        gsm[r0t]       = s1a;  gsm[64 + r0t]      = s2a;
        gsm[r0t + 8]   = s1b;  gsm[64 + r0t + 8]  = s2b;
    }
    __syncthreads();
    float mx = -3.0e38f;
    if (nhalf == 0 && tID == 0) {
        float f1t = s1a + gsm[r0t],     f2t = s2a + gsm[64 + r0t];
        float f1u = s1b + gsm[r0t + 8], f2u = s2b + gsm[64 + r0t + 8];
        d_f1[i0 + r0t]     = f1t;  d_f2[i0 + r0t]     = f2t;
        d_f1[i0 + r0t + 8] = f1u;  d_f2[i0 + r0t + 8] = f2u;
        mx = fmaxf(f2t, f2u);
    }
#pragma unroll
    for (int o = 16; o; o >>= 1)
        mx = fmaxf(mx, __shfl_xor_sync(0xffffffffu, mx, o));
    if (lane == 0) gsm[128 + wid] = mx;
    __syncthreads();
    if (t == 0) {
        float m = gsm[128];
#pragma unroll
        for (int w = 1; w < 8; w++) m = fmaxf(m, gsm[128 + w]);
        int b = __float_as_int(m);
        int key = b >= 0 ? b : (b ^ 0x7fffffff);
        atomicMax(&d_gmaxkey, key);
    }
}

// ---------------- factorized softmax weights ----------------
__global__ void pexp_kernel() {
    int i = blockIdx.x * 256 + threadIdx.x;
    int kk = d_gmaxkey;
    float gm = __int_as_float(kk >= 0 ? kk : (kk ^ 0x7fffffff));
    float f1 = d_f1[i], f2 = d_f2[i];
    float u  = f1 + gm;
    float m  = u > 0.f ? u : LALPHA * u;
    d_A[i] = __expf(u - m);
    d_C[i] = __expf(LALPHA * u - m);
    float v = f2 - gm;
    d_B[i] = __expf(v);
    d_D[i] = __expf(LALPHA * v);
}

// ---------------- staging helpers (cp.async) ----------------
__device__ __forceinline__ void stage_slot(uint32_t sbase, const int* adj,
                                           int s, int t) {
    int buf = s & 1;
    int ib  = s >> 7;
    int jg  = (s & (CPB - 1)) * KC;
    uint32_t wb = sbase + (uint32_t)(buf * WHTILE_WORDS * 4);
#pragma unroll
    for (int u = 0; u < 8; u++) {
        int f = u * 512 + t;
        int row = f >> 6, c4 = (f & 63) << 2;
        cp_async16(wb + (uint32_t)((row * WS_STRIDE + c4) * 4),
                   &d_Whr[(size_t)(jg + row) * FOUT + c4]);
    }
    uint32_t ab = sbase + (uint32_t)((SM_ADJ + buf * ADJTILE_WORDS) * 4);
    const int* abase = adj + (size_t)ib * M_TILE * Nn + jg;
#pragma unroll
    for (int u = 0; u < 4; u++) {
        int f = u * 512 + t;
        int row = f >> 4, seg = (f & 15) << 2;
        cp_async16(ab + (uint32_t)((row * ADJ_STRIDE + seg) * 4),
                   abase + (size_t)row * Nn + seg);
    }
    if (t < 48) {
        uint32_t fb = sbase + (uint32_t)((SM_FBD + buf * 192 + t * 4) * 4);
        const float* src = (t < 16) ? &d_f2[jg + t * 4]
                         : (t < 32) ? &d_B[jg + (t - 16) * 4]
                                    : &d_D[jg + (t - 32) * 4];
        cp_async16(fb, src);
    }
}

// ---------------- fused attention @ Wh via mma.sync tf32 ----------------
__global__ void __launch_bounds__(512, 1) attn_mma(const int* __restrict__ adj) {
    extern __shared__ float sm[];
    uint32_t sbase = smem_u32(sm);

    int t    = threadIdx.x;
    int lane = t & 31, wid = t >> 5;
    int mstrip = wid >> 1, nhalf = wid & 1;
    int gID = lane >> 2, tID = lane & 3;
    int r0t = mstrip * 16 + gID;

    int s0 = (int)(((long long)blockIdx.x * TOTSLOT) / NCTA);
    int s1 = (int)(((long long)(blockIdx.x + 1) * TOTSLOT) / NCTA);

    float acc[16][4];
#pragma unroll
    for (int n = 0; n < 16; n++)
#pragma unroll
        for (int u = 0; u < 4; u++) acc[n][u] = 0.f;
    float ssum0 = 0.f, ssum1 = 0.f;

    float f1a = 0.f, Aa = 0.f, Ca = 0.f;
    float f1b = 0.f, Ab = 0.f, Cb = 0.f;
    int cur_ib = -1;

    stage_slot(sbase, adj, s0, t);
    cp_commit();

    for (int s = s0; s < s1; s++) {
        int ib = s >> 7;
        int buf = s & 1;

        if (ib != cur_ib) {
            if (cur_ib >= 0) {
                float sa = ssum0 + __shfl_xor_sync(0xffffffffu, ssum0, 1);
                sa += __shfl_xor_sync(0xffffffffu, sa, 2);
                float sb = ssum1 + __shfl_xor_sync(0xffffffffu, ssum1, 1);
                sb += __shfl_xor_sync(0xffffffffu, sb, 2);
                int base = cur_ib * M_TILE;
                if (tID == 0 && nhalf == 0) {
                    atomicAdd(&d_ssum[base + r0t], sa);
                    atomicAdd(&d_ssum[base + r0t + 8], sb);
                }
                float* np = &d_num[(size_t)(base) * FOUT];
                int cb = nhalf * 128 + tID * 2;
#pragma unroll
                for (int n = 0; n < 16; n++) {
                    int cc = cb + n * 8;
                    atomicAdd(&np[(size_t)r0t * FOUT + cc],       acc[n][0]);
                    atomicAdd(&np[(size_t)r0t * FOUT + cc + 1],   acc[n][1]);
                    atomicAdd(&np[(size_t)(r0t + 8) * FOUT + cc],     acc[n][2]);
                    atomicAdd(&np[(size_t)(r0t + 8) * FOUT + cc + 1], acc[n][3]);
                }
#pragma unroll
                for (int n = 0; n < 16; n++)
#pragma unroll
                    for (int u = 0; u < 4; u++) acc[n][u] = 0.f;
                ssum0 = 0.f; ssum1 = 0.f;
            }
            int base = ib * M_TILE;
            f1a = d_f1[base + r0t];     f1b = d_f1[base + r0t + 8];
            Aa  = d_A[base + r0t];      Ab  = d_A[base + r0t + 8];
            Ca  = d_C[base + r0t];      Cb  = d_C[base + r0t + 8];
            cur_ib = ib;
        }

        cp_wait<0>();
        __syncthreads();

        if (s + 1 < s1) {
            stage_slot(sbase, adj, s + 1, t);
            cp_commit();
        }

        const float* Wb   = sm + buf * WHTILE_WORDS;
        const int*   adjS = (const int*)(sm + SM_ADJ + buf * ADJTILE_WORDS);
        const float* fbd  = sm + SM_FBD + buf * 192;

#pragma unroll
        for (int k = 0; k < 8; k++) {
            int j0 = tID + 8 * k, j1 = j0 + 4;
            int ad00 = adjS[r0t * ADJ_STRIDE + j0];
            int ad10 = adjS[(r0t + 8) * ADJ_STRIDE + j0];
            int ad01 = adjS[r0t * ADJ_STRIDE + j1];
            int ad11 = adjS[(r0t + 8) * ADJ_STRIDE + j1];
            float f20 = fbd[j0], B0 = fbd[64 + j0], D0 = fbd[128 + j0];
            float f21 = fbd[j1], B1 = fbd[64 + j1], D1 = fbd[128 + j1];
            float e00 = f1a + f20, e10 = f1b + f20;
            float e01 = f1a + f21, e11 = f1b + f21;
            float p00 = (ad00 > 0) ? (e00 > 0.f ? Aa * B0 : Ca * D0) : 0.f;
            float p10 = (ad10 > 0) ? (e10 > 0.f ? Ab * B0 : Cb * D0) : 0.f;
            float p01 = (ad01 > 0) ? (e01 > 0.f ? Aa * B1 : Ca * D1) : 0.f;
            float p11 = (ad11 > 0) ? (e11 > 0.f ? Ab * B1 : Cb * D1) : 0.f;
            if (nhalf == 0) { ssum0 += p00 + p01; ssum1 += p10 + p11; }
            uint32_t a0 = tf32_bits(p00), a1 = tf32_bits(p10);
            uint32_t a2 = tf32_bits(p01), a3 = tf32_bits(p11);
            int krow = k * 8 + tID;
#pragma unroll
            for (int n = 0; n < 16; n++) {
                int n0 = nhalf * 128 + n * 8 + gID;
                uint32_t b0 = __float_as_uint(Wb[krow * WS_STRIDE + n0]);
                uint32_t b1 = __float_as_uint(Wb[(krow + 4) * WS_STRIDE + n0]);
                mma_tf32(acc[n], a0, a1, a2, a3, b0, b1);
            }
        }
    }

    {
        float sa = ssum0 + __shfl_xor_sync(0xffffffffu, ssum0, 1);
        sa += __shfl_xor_sync(0xffffffffu, sa, 2);
        float sb = ssum1 + __shfl_xor_sync(0xffffffffu, ssum1, 1);
        sb += __shfl_xor_sync(0xffffffffu, sb, 2);
        int base = cur_ib * M_TILE;
        if (tID == 0 && nhalf == 0) {
            atomicAdd(&d_ssum[base + r0t], sa);
            atomicAdd(&d_ssum[base + r0t + 8], sb);
        }
        float* np = &d_num[(size_t)(base) * FOUT];
        int cb = nhalf * 128 + tID * 2;
#pragma unroll
        for (int n = 0; n < 16; n++) {
            int cc = cb + n * 8;
            atomicAdd(&np[(size_t)r0t * FOUT + cc],       acc[n][0]);
            atomicAdd(&np[(size_t)r0t * FOUT + cc + 1],   acc[n][1]);
            atomicAdd(&np[(size_t)(r0t + 8) * FOUT + cc],     acc[n][2]);
            atomicAdd(&np[(size_t)(r0t + 8) * FOUT + cc + 1], acc[n][3]);
        }
    }
}

// ---------------- normalize + ELU (vectorized) ----------------
__global__ void elu_kernel(float* __restrict__ out) {
    int idx = blockIdx.x * 256 + threadIdx.x;     // one float4 per thread
    int row = idx >> 6;                           // 64 float4 per row
    float s = d_ssum[row];
    float4 v = *(const float4*)&d_num[(size_t)idx * 4];
    float4 o;
    float x;
    x = v.x / s; o.x = x > 0.f ? x : expm1f(x);
    x = v.y / s; o.y = x > 0.f ? x : expm1f(x);
    x = v.z / s; o.z = x > 0.f ? x : expm1f(x);
    x = v.w / s; o.w = x > 0.f ? x : expm1f(x);
    *(float4*)&out[(size_t)idx * 4] = o;
}

extern "C" void kernel_launch(void* const* d_in, const int* in_sizes, int n_in,
                              void* d_out, int out_size) {
    const float* h   = (const float*)d_in[0];
    const int*   adj = (const int*)d_in[1];
    const float* W   = (const float*)d_in[2];
    const float* a   = (const float*)d_in[3];
    float* out = (float*)d_out;

    cudaFuncSetAttribute(attn_mma, cudaFuncAttributeMaxDynamicSharedMemorySize, SMEM_DYN);
    cudaFuncSetAttribute(gemm_wh_mma, cudaFuncAttributeMaxDynamicSharedMemorySize, GSMEM_DYN);

    init_kernel<<<(Nn * FOUT) / 1024, 256>>>(W);
    gemm_wh_mma<<<Nn / GM, 256, GSMEM_DYN>>>(h, a);
    pexp_kernel<<<Nn / 256, 256>>>();
    attn_mma<<<NCTA, 512, SMEM_DYN>>>(adj);
    elu_kernel<<<(Nn * FOUT) / 1024, 256>>>(out);
}